// round 8
// baseline (speedup 1.0000x reference)
#include <cuda_runtime.h>
#include <cuda_bf16.h>
#include <cstdint>

#define BB   1024
#define TT   256
#define CC   384
#define HS   64

// Pre-split scratch for attention (device globals: allocation-free).
__device__ __align__(16) __nv_bfloat16 QhG[BB * TT * HS], QlG[BB * TT * HS];
__device__ __align__(16) __nv_bfloat16 KhG[BB * TT * HS], KlG[BB * TT * HS];
__device__ __align__(16) __nv_bfloat16 VthG[BB * HS * TT], VtlG[BB * HS * TT]; // [b][hs][t]
__device__ __align__(16) float WallG[384 * 192];   // W concat (tf32-rounded), layout [k][n]

// ---------------- helpers ----------------
__device__ __forceinline__ uint32_t smem_u32(const void* p) {
    uint32_t a;
    asm("{ .reg .u64 t; cvta.to.shared.u64 t, %1; cvt.u32.u64 %0, t; }" : "=r"(a) : "l"(p));
    return a;
}
__device__ __forceinline__ void cp16(uint32_t dst, const void* src) {
    asm volatile("cp.async.ca.shared.global [%0], [%1], 16;" :: "r"(dst), "l"(src) : "memory");
}
#define CP_COMMIT() asm volatile("cp.async.commit_group;" ::: "memory")
#define CP_WAIT1()  asm volatile("cp.async.wait_group 1;" ::: "memory")
#define CP_WAIT0()  asm volatile("cp.async.wait_group 0;" ::: "memory")

// round fp32 to tf32 (round-to-nearest-even on the 19-bit field)
__device__ __forceinline__ uint32_t rna_tf32(uint32_t x) {
    uint32_t r;
    asm("cvt.rna.tf32.f32 %0, %1;" : "=r"(r) : "r"(x));
    return r;
}
__device__ __forceinline__ float rna_tf32_f(float x) {
    float r;
    asm("cvt.rna.tf32.f32 %0, %1;" : "=f"(r) : "f"(x));
    return r;
}

// fp32 pair -> packed bf16 hi / lo pair.
__device__ __forceinline__ void split2(float a, float b, uint32_t& h, uint32_t& l) {
    __nv_bfloat162 hh = __floats2bfloat162_rn(a, b);
    float ra = a - __bfloat162float(hh.x);
    float rb = b - __bfloat162float(hh.y);
    __nv_bfloat162 ll = __floats2bfloat162_rn(ra, rb);
    h = *reinterpret_cast<uint32_t*>(&hh);
    l = *reinterpret_cast<uint32_t*>(&ll);
}

// exp2(x) for x <= 0, FMA pipe only.
__device__ __forceinline__ float fexp2f(float x) {
    x = fmaxf(x, -125.0f);
    float fi = floorf(x);
    float f = x - fi;
    float p = 0.0018775767f;
    p = fmaf(p, f, 0.0089893397f);
    p = fmaf(p, f, 0.055826318f);
    p = fmaf(p, f, 0.24015361f);
    p = fmaf(p, f, 0.69315308f);
    p = fmaf(p, f, 1.0f);
    return p * __int_as_float(((int)fi + 127) << 23);
}
#define SCALE2 0.18033688f   // 0.125 * log2(e)

// bf16 m16n8k16 MMA
__device__ __forceinline__ void mma16816(float& c0, float& c1, float& c2, float& c3,
                                         uint32_t a0, uint32_t a1, uint32_t a2, uint32_t a3,
                                         uint32_t b0, uint32_t b1) {
    asm volatile(
        "mma.sync.aligned.m16n8k16.row.col.f32.bf16.bf16.f32 "
        "{%0,%1,%2,%3}, {%4,%5,%6,%7}, {%8,%9}, {%0,%1,%2,%3};"
        : "+f"(c0), "+f"(c1), "+f"(c2), "+f"(c3)
        : "r"(a0), "r"(a1), "r"(a2), "r"(a3), "r"(b0), "r"(b1));
}

// tf32 m16n8k8 MMA
__device__ __forceinline__ void mma16808t(float* c,
                                          uint32_t a0, uint32_t a1, uint32_t a2, uint32_t a3,
                                          uint32_t b0, uint32_t b1) {
    asm volatile(
        "mma.sync.aligned.m16n8k8.row.col.f32.tf32.tf32.f32 "
        "{%0,%1,%2,%3}, {%4,%5,%6,%7}, {%8,%9}, {%0,%1,%2,%3};"
        : "+f"(c[0]), "+f"(c[1]), "+f"(c[2]), "+f"(c[3])
        : "r"(a0), "r"(a1), "r"(a2), "r"(a3), "r"(b0), "r"(b1));
}

// ============================================================================
// Kernel 0: concat W into fp32 [k=384][n=192], tf32-RNA-rounded.
// ============================================================================
__global__ void prep_w(const float* __restrict__ Wq,
                       const float* __restrict__ Wk,
                       const float* __restrict__ Wv)
{
    int idx = blockIdx.x * blockDim.x + threadIdx.x;
    if (idx >= 384 * 192) return;
    int k = idx / 192;
    int n = idx % 192;
    int m = n >> 6, hs = n & 63;
    const float* W = (m == 0) ? Wq : ((m == 1) ? Wk : Wv);
    WallG[idx] = rna_tf32_f(W[k * HS + hs]);
}

// ============================================================================
// Kernel 1: QKV projection, 1xTF32 (m16n8k8, RNA-rounded operands),
// cp.async double-buffered. Grid 2048, 256 thr. CTA tile 128x192.
// ============================================================================
#define ASTRIDE 40
#define BSTRIDE 200
#define AOFFB 0
#define BOFFB 20480
#define QBUF  46080
#define QKV_SMEM (2 * QBUF)         // 92160 B

__global__ __launch_bounds__(256, 2)
void qkv_mma(const float* __restrict__ X)
{
    extern __shared__ char sm[];
    const int tid  = threadIdx.x;
    const int lane = tid & 31;
    const int w    = tid >> 5;
    const int m0   = (w >> 1) * 32;
    const int n0   = (w & 1) * 96;
    const int gid  = lane >> 2;
    const int tg   = lane & 3;
    const size_t row0 = (size_t)blockIdx.x * 128;
    const uint32_t sb = smem_u32(sm);

    auto stage = [&](int c, int buf) {
        const int k0 = c * 32;
        const uint32_t base = sb + buf * QBUF;
#pragma unroll
        for (int it = 0; it < 4; it++) {
            int i  = tid + 256 * it;
            int r  = i >> 3;
            int c4 = (i & 7) << 2;
            cp16(base + AOFFB + (uint32_t)(r * ASTRIDE + c4) * 4,
                 &X[(row0 + r) * CC + k0 + c4]);
        }
#pragma unroll
        for (int it = 0; it < 6; it++) {
            int i  = tid + 256 * it;
            int r  = i / 48;
            int c4 = (i % 48) << 2;
            cp16(base + BOFFB + (uint32_t)(r * BSTRIDE + c4) * 4,
                 &WallG[(size_t)(k0 + r) * 192 + c4]);
        }
        CP_COMMIT();
    };

    float acc[2][12][4] = {};

    stage(0, 0);
#pragma unroll 1
    for (int c = 0; c < 12; c++) {
        if (c < 11) { stage(c + 1, (c + 1) & 1); CP_WAIT1(); } else { CP_WAIT0(); }
        __syncthreads();
        const int buf = c & 1;
        const uint32_t* A = reinterpret_cast<const uint32_t*>(sm + buf * QBUF + AOFFB);
        const uint32_t* B = reinterpret_cast<const uint32_t*>(sm + buf * QBUF + BOFFB);

#pragma unroll
        for (int ks = 0; ks < 4; ks++) {
            const int kc = ks * 8 + tg;
            uint32_t a[2][4];
#pragma unroll
            for (int mt = 0; mt < 2; mt++) {
                const int r = m0 + mt * 16 + gid;
                a[mt][0] = rna_tf32(A[r * ASTRIDE + kc]);
                a[mt][1] = rna_tf32(A[(r + 8) * ASTRIDE + kc]);
                a[mt][2] = rna_tf32(A[r * ASTRIDE + kc + 4]);
                a[mt][3] = rna_tf32(A[(r + 8) * ASTRIDE + kc + 4]);
            }
#pragma unroll
            for (int nt = 0; nt < 12; nt++) {
                const int col = n0 + nt * 8 + gid;
                uint32_t b0 = B[kc * BSTRIDE + col];
                uint32_t b1 = B[(kc + 4) * BSTRIDE + col];
                mma16808t(acc[0][nt], a[0][0], a[0][1], a[0][2], a[0][3], b0, b1);
                mma16808t(acc[1][nt], a[1][0], a[1][1], a[1][2], a[1][3], b0, b1);
            }
        }
        __syncthreads();
    }

    // --- epilogue: split to bf16 hi/lo, store Q/K row-major, V transposed ---
#pragma unroll
    for (int nt = 0; nt < 12; nt++) {
        const int colg = n0 + nt * 8 + 2 * tg;
        const int mat  = colg >> 6;
        const int hs0  = colg & 63;
#pragma unroll
        for (int mt = 0; mt < 2; mt++) {
            const size_t rowA = row0 + m0 + mt * 16 + gid;
            const size_t rowB = rowA + 8;
            const float* cc = acc[mt][nt];
            if (mat == 2) {
                const size_t baseA = (rowA >> 8) * (size_t)(HS * TT) + (rowA & 255);
                const size_t baseB = (rowB >> 8) * (size_t)(HS * TT) + (rowB & 255);
#pragma unroll
                for (int e = 0; e < 4; e++) {
                    const float v = cc[e];
                    __nv_bfloat16 h = __float2bfloat16(v);
                    __nv_bfloat16 l = __float2bfloat16(v - __bfloat162float(h));
                    const size_t base = (e < 2) ? baseA : baseB;
                    const size_t off  = base + (size_t)(hs0 + (e & 1)) * TT;
                    VthG[off] = h;
                    VtlG[off] = l;
                }
            } else {
                __nv_bfloat16* dh = (mat == 0) ? QhG : KhG;
                __nv_bfloat16* dl = (mat == 0) ? QlG : KlG;
                uint32_t h, l;
                split2(cc[0], cc[1], h, l);
                *reinterpret_cast<uint32_t*>(&dh[rowA * HS + hs0]) = h;
                *reinterpret_cast<uint32_t*>(&dl[rowA * HS + hs0]) = l;
                split2(cc[2], cc[3], h, l);
                *reinterpret_cast<uint32_t*>(&dh[rowB * HS + hs0]) = h;
                *reinterpret_cast<uint32_t*>(&dl[rowB * HS + hs0]) = l;
            }
        }
    }
}

// ============================================================================
// Kernel 2: FA2 attention (3-pass split bf16), cp.async double-buffered
// 64-key chunks. Grid (2, 1024), 256 thr = 8 warps x 16 query rows.
// ============================================================================
#define KP 72
#define ABUF 36864                      // Kh|Kl|Vh|Vl, each 64*KP*2 = 9216 B
#define ATTN_SMEM (2 * ABUF)            // 73728

__global__ __launch_bounds__(256, 1)
void attn_mma(float* __restrict__ out)
{
    extern __shared__ char sm[];
    const uint32_t sb = smem_u32(sm);
    const int half = blockIdx.x;
    const int b    = blockIdx.y;
    const int tid  = threadIdx.x;
    const int lane = tid & 31;
    const int w    = tid >> 5;
    const int gid  = lane >> 2;
    const int tg   = lane & 3;
    const int qb   = half * 128 + w * 16;

    auto stage = [&](int c, int buf) {
        const int kn0 = c * 64;
#pragma unroll
        for (int it = 0; it < 8; it++) {
            int i   = tid + 256 * it;
            int arr = i >> 9;
            int rem = i & 511;
            int r   = rem >> 3;
            int c8  = (rem & 7) << 3;
            uint32_t dst = sb + buf * ABUF + arr * 9216 + (uint32_t)(r * KP + c8) * 2;
            const __nv_bfloat16* src;
            if (arr == 0)      src = &KhG[((size_t)b * TT + kn0 + r) * HS + c8];
            else if (arr == 1) src = &KlG[((size_t)b * TT + kn0 + r) * HS + c8];
            else if (arr == 2) src = &VthG[((size_t)b * HS + r) * TT + kn0 + c8];
            else               src = &VtlG[((size_t)b * HS + r) * TT + kn0 + c8];
            cp16(dst, src);
        }
        CP_COMMIT();
    };

    // Q fragments direct from pre-split global.
    uint32_t qh[4][4], ql[4][4];
    {
        const size_t r0 = (size_t)b * TT + qb + gid;
#pragma unroll
        for (int ks = 0; ks < 4; ks++) {
            const int o = ks * 16 + 2 * tg;
            qh[ks][0] = *reinterpret_cast<const uint32_t*>(&QhG[r0 * HS + o]);
            qh[ks][1] = *reinterpret_cast<const uint32_t*>(&QhG[(r0 + 8) * HS + o]);
            qh[ks][2] = *reinterpret_cast<const uint32_t*>(&QhG[r0 * HS + o + 8]);
            qh[ks][3] = *reinterpret_cast<const uint32_t*>(&QhG[(r0 + 8) * HS + o + 8]);
            ql[ks][0] = *reinterpret_cast<const uint32_t*>(&QlG[r0 * HS + o]);
            ql[ks][1] = *reinterpret_cast<const uint32_t*>(&QlG[(r0 + 8) * HS + o]);
            ql[ks][2] = *reinterpret_cast<const uint32_t*>(&QlG[r0 * HS + o + 8]);
            ql[ks][3] = *reinterpret_cast<const uint32_t*>(&QlG[(r0 + 8) * HS + o + 8]);
        }
    }

    float O[32];
#pragma unroll
    for (int i = 0; i < 32; i++) O[i] = 0.f;
    float mr0 = -1e30f, mr1 = -1e30f, l0 = 0.f, l1 = 0.f;

    const int nch = (half + 1) * 2;
    stage(0, 0);
#pragma unroll 1
    for (int c = 0; c < nch; c++) {
        if (c < nch - 1) { stage(c + 1, (c + 1) & 1); CP_WAIT1(); } else { CP_WAIT0(); }
        __syncthreads();
        const int kn0 = c * 64;
        const int buf = c & 1;
        const __nv_bfloat16* Khs = reinterpret_cast<const __nv_bfloat16*>(sm + buf * ABUF);
        const __nv_bfloat16* Kls = reinterpret_cast<const __nv_bfloat16*>(sm + buf * ABUF + 9216);
        const __nv_bfloat16* Vhs = reinterpret_cast<const __nv_bfloat16*>(sm + buf * ABUF + 18432);
        const __nv_bfloat16* Vls = reinterpret_cast<const __nv_bfloat16*>(sm + buf * ABUF + 27648);

        if (kn0 <= qb) {
            // ---- scores ----
            float s[32];
#pragma unroll
            for (int nt = 0; nt < 8; nt++) {
                float c0 = 0.f, c1 = 0.f, c2 = 0.f, c3 = 0.f;
                const int bn = nt * 8 + gid;
#pragma unroll
                for (int ks = 0; ks < 4; ks++) {
                    uint32_t bh0 = *reinterpret_cast<const uint32_t*>(&Khs[bn * KP + ks * 16 + 2 * tg]);
                    uint32_t bh1 = *reinterpret_cast<const uint32_t*>(&Khs[bn * KP + ks * 16 + 2 * tg + 8]);
                    uint32_t bl0 = *reinterpret_cast<const uint32_t*>(&Kls[bn * KP + ks * 16 + 2 * tg]);
                    uint32_t bl1 = *reinterpret_cast<const uint32_t*>(&Kls[bn * KP + ks * 16 + 2 * tg + 8]);
                    mma16816(c0, c1, c2, c3, qh[ks][0], qh[ks][1], qh[ks][2], qh[ks][3], bh0, bh1);
                    mma16816(c0, c1, c2, c3, qh[ks][0], qh[ks][1], qh[ks][2], qh[ks][3], bl0, bl1);
                    mma16816(c0, c1, c2, c3, ql[ks][0], ql[ks][1], ql[ks][2], ql[ks][3], bh0, bh1);
                }
                s[nt * 4 + 0] = c0 * SCALE2;
                s[nt * 4 + 1] = c1 * SCALE2;
                s[nt * 4 + 2] = c2 * SCALE2;
                s[nt * 4 + 3] = c3 * SCALE2;
            }
            if (kn0 + 63 > qb) {
                const int r0 = qb + gid, r1 = qb + 8 + gid;
#pragma unroll
                for (int nt = 0; nt < 8; nt++) {
                    const int col = kn0 + nt * 8 + 2 * tg;
                    if (col     > r0) s[nt * 4 + 0] = -1e30f;
                    if (col + 1 > r0) s[nt * 4 + 1] = -1e30f;
                    if (col     > r1) s[nt * 4 + 2] = -1e30f;
                    if (col + 1 > r1) s[nt * 4 + 3] = -1e30f;
                }
            }
            // ---- online softmax (base-2) ----
            float c0m = -1e30f, c1m = -1e30f;
#pragma unroll
            for (int nt = 0; nt < 8; nt++) {
                c0m = fmaxf(c0m, fmaxf(s[nt * 4 + 0], s[nt * 4 + 1]));
                c1m = fmaxf(c1m, fmaxf(s[nt * 4 + 2], s[nt * 4 + 3]));
            }
            c0m = fmaxf(c0m, __shfl_xor_sync(0xffffffffu, c0m, 1));
            c0m = fmaxf(c0m, __shfl_xor_sync(0xffffffffu, c0m, 2));
            c1m = fmaxf(c1m, __shfl_xor_sync(0xffffffffu, c1m, 1));
            c1m = fmaxf(c1m, __shfl_xor_sync(0xffffffffu, c1m, 2));
            const float mn0 = fmaxf(mr0, c0m), mn1 = fmaxf(mr1, c1m);
            const float corr0 = fexp2f(mr0 - mn0), corr1 = fexp2f(mr1 - mn1);
            mr0 = mn0; mr1 = mn1;

            float sum0 = 0.f, sum1 = 0.f;
#pragma unroll
            for (int nt = 0; nt < 8; nt++) {
                float p0 = fexp2f(s[nt * 4 + 0] - mn0);
                float p1 = fexp2f(s[nt * 4 + 1] - mn0);
                float p2 = fexp2f(s[nt * 4 + 2] - mn1);
                float p3 = fexp2f(s[nt * 4 + 3] - mn1);
                s[nt * 4 + 0] = p0; s[nt * 4 + 1] = p1;
                s[nt * 4 + 2] = p2; s[nt * 4 + 3] = p3;
                sum0 += p0 + p1; sum1 += p2 + p3;
            }
            sum0 += __shfl_xor_sync(0xffffffffu, sum0, 1);
            sum0 += __shfl_xor_sync(0xffffffffu, sum0, 2);
            sum1 += __shfl_xor_sync(0xffffffffu, sum1, 1);
            sum1 += __shfl_xor_sync(0xffffffffu, sum1, 2);
            l0 = l0 * corr0 + sum0;
            l1 = l1 * corr1 + sum1;
#pragma unroll
            for (int hn = 0; hn < 8; hn++) {
                O[hn * 4 + 0] *= corr0; O[hn * 4 + 1] *= corr0;
                O[hn * 4 + 2] *= corr1; O[hn * 4 + 3] *= corr1;
            }
            // ---- PV ----
#pragma unroll
            for (int ks = 0; ks < 4; ks++) {
                uint32_t ph[4], pl[4];
                split2(s[(2 * ks) * 4 + 0],     s[(2 * ks) * 4 + 1],     ph[0], pl[0]);
                split2(s[(2 * ks) * 4 + 2],     s[(2 * ks) * 4 + 3],     ph[1], pl[1]);
                split2(s[(2 * ks + 1) * 4 + 0], s[(2 * ks + 1) * 4 + 1], ph[2], pl[2]);
                split2(s[(2 * ks + 1) * 4 + 2], s[(2 * ks + 1) * 4 + 3], ph[3], pl[3]);
#pragma unroll
                for (int hn = 0; hn < 8; hn++) {
                    const int vn = hn * 8 + gid;
                    uint32_t vh0 = *reinterpret_cast<const uint32_t*>(&Vhs[vn * KP + ks * 16 + 2 * tg]);
                    uint32_t vh1 = *reinterpret_cast<const uint32_t*>(&Vhs[vn * KP + ks * 16 + 2 * tg + 8]);
                    uint32_t vl0 = *reinterpret_cast<const uint32_t*>(&Vls[vn * KP + ks * 16 + 2 * tg]);
                    uint32_t vl1 = *reinterpret_cast<const uint32_t*>(&Vls[vn * KP + ks * 16 + 2 * tg + 8]);
                    float* o = &O[hn * 4];
                    mma16816(o[0], o[1], o[2], o[3], ph[0], ph[1], ph[2], ph[3], vh0, vh1);
                    mma16816(o[0], o[1], o[2], o[3], pl[0], pl[1], pl[2], pl[3], vh0, vh1);
                    mma16816(o[0], o[1], o[2], o[3], ph[0], ph[1], ph[2], ph[3], vl0, vl1);
                }
            }
        }
        __syncthreads();
    }

    const float i0 = 1.f / l0, i1 = 1.f / l1;
    float* o0 = out + ((size_t)b * TT + qb + gid) * HS;
    float* o1 = o0 + 8 * HS;
#pragma unroll
    for (int hn = 0; hn < 8; hn++) {
        *reinterpret_cast<float2*>(&o0[hn * 8 + 2 * tg]) =
            make_float2(O[hn * 4 + 0] * i0, O[hn * 4 + 1] * i0);
        *reinterpret_cast<float2*>(&o1[hn * 8 + 2 * tg]) =
            make_float2(O[hn * 4 + 2] * i1, O[hn * 4 + 3] * i1);
    }
}

// ============================================================================
extern "C" void kernel_launch(void* const* d_in, const int* in_sizes, int n_in,
                              void* d_out, int out_size)
{
    const float* x  = (const float*)d_in[0];
    const float* Wq = (const float*)d_in[1];
    const float* Wk = (const float*)d_in[2];
    const float* Wv = (const float*)d_in[3];
    float* out = (float*)d_out;

    (void)in_sizes; (void)n_in; (void)out_size;

    prep_w<<<(384 * 192 + 255) / 256, 256>>>(Wq, Wk, Wv);

    cudaFuncSetAttribute(qkv_mma, cudaFuncAttributeMaxDynamicSharedMemorySize, QKV_SMEM);
    qkv_mma<<<2048, 256, QKV_SMEM>>>(x);

    cudaFuncSetAttribute(attn_mma, cudaFuncAttributeMaxDynamicSharedMemorySize, ATTN_SMEM);
    dim3 agrid(2, BB);
    attn_mma<<<agrid, 256, ATTN_SMEM>>>(out);
}

// round 9
// speedup vs baseline: 1.0698x; 1.0698x over previous
#include <cuda_runtime.h>
#include <cuda_bf16.h>
#include <cstdint>

#define BB   1024
#define TT   256
#define CC   384
#define HS   64

// Scratch (device globals: allocation-free).
__device__ __align__(16) float QfG[BB * TT * HS];   // Q, tf32-RNA-rounded fp32
__device__ __align__(16) float KfG[BB * TT * HS];   // K, tf32-RNA-rounded fp32
__device__ __align__(16) __nv_bfloat16 VthG[BB * HS * TT], VtlG[BB * HS * TT]; // V^T hi/lo
__device__ __align__(16) float WallG[384 * 192];    // W concat (tf32-rounded), [k][n]

// ---------------- helpers ----------------
__device__ __forceinline__ uint32_t smem_u32(const void* p) {
    uint32_t a;
    asm("{ .reg .u64 t; cvta.to.shared.u64 t, %1; cvt.u32.u64 %0, t; }" : "=r"(a) : "l"(p));
    return a;
}
__device__ __forceinline__ void cp16(uint32_t dst, const void* src) {
    asm volatile("cp.async.ca.shared.global [%0], [%1], 16;" :: "r"(dst), "l"(src) : "memory");
}
#define CP_COMMIT() asm volatile("cp.async.commit_group;" ::: "memory")
#define CP_WAIT1()  asm volatile("cp.async.wait_group 1;" ::: "memory")
#define CP_WAIT0()  asm volatile("cp.async.wait_group 0;" ::: "memory")

__device__ __forceinline__ uint32_t rna_tf32(uint32_t x) {
    uint32_t r;
    asm("cvt.rna.tf32.f32 %0, %1;" : "=r"(r) : "r"(x));
    return r;
}
__device__ __forceinline__ float rna_tf32_f(float x) {
    float r;
    asm("cvt.rna.tf32.f32 %0, %1;" : "=f"(r) : "f"(x));
    return r;
}

// fp32 pair -> packed bf16 hi / lo pair.
__device__ __forceinline__ void split2(float a, float b, uint32_t& h, uint32_t& l) {
    __nv_bfloat162 hh = __floats2bfloat162_rn(a, b);
    float ra = a - __bfloat162float(hh.x);
    float rb = b - __bfloat162float(hh.y);
    __nv_bfloat162 ll = __floats2bfloat162_rn(ra, rb);
    h = *reinterpret_cast<uint32_t*>(&hh);
    l = *reinterpret_cast<uint32_t*>(&ll);
}

// exp2(x) for x <= 0, FMA pipe only.
__device__ __forceinline__ float fexp2f(float x) {
    x = fmaxf(x, -125.0f);
    float fi = floorf(x);
    float f = x - fi;
    float p = 0.0018775767f;
    p = fmaf(p, f, 0.0089893397f);
    p = fmaf(p, f, 0.055826318f);
    p = fmaf(p, f, 0.24015361f);
    p = fmaf(p, f, 0.69315308f);
    p = fmaf(p, f, 1.0f);
    return p * __int_as_float(((int)fi + 127) << 23);
}
#define SCALE2 0.18033688f   // 0.125 * log2(e)

// bf16 m16n8k16 MMA
__device__ __forceinline__ void mma16816(float& c0, float& c1, float& c2, float& c3,
                                         uint32_t a0, uint32_t a1, uint32_t a2, uint32_t a3,
                                         uint32_t b0, uint32_t b1) {
    asm volatile(
        "mma.sync.aligned.m16n8k16.row.col.f32.bf16.bf16.f32 "
        "{%0,%1,%2,%3}, {%4,%5,%6,%7}, {%8,%9}, {%0,%1,%2,%3};"
        : "+f"(c0), "+f"(c1), "+f"(c2), "+f"(c3)
        : "r"(a0), "r"(a1), "r"(a2), "r"(a3), "r"(b0), "r"(b1));
}

// tf32 m16n8k8 MMA
__device__ __forceinline__ void mma16808t(float* c,
                                          uint32_t a0, uint32_t a1, uint32_t a2, uint32_t a3,
                                          uint32_t b0, uint32_t b1) {
    asm volatile(
        "mma.sync.aligned.m16n8k8.row.col.f32.tf32.tf32.f32 "
        "{%0,%1,%2,%3}, {%4,%5,%6,%7}, {%8,%9}, {%0,%1,%2,%3};"
        : "+f"(c[0]), "+f"(c[1]), "+f"(c[2]), "+f"(c[3])
        : "r"(a0), "r"(a1), "r"(a2), "r"(a3), "r"(b0), "r"(b1));
}

// ============================================================================
// Kernel 0: concat W into fp32 [k=384][n=192], tf32-RNA-rounded.
// ============================================================================
__global__ void prep_w(const float* __restrict__ Wq,
                       const float* __restrict__ Wk,
                       const float* __restrict__ Wv)
{
    int idx = blockIdx.x * blockDim.x + threadIdx.x;
    if (idx >= 384 * 192) return;
    int k = idx / 192;
    int n = idx % 192;
    int m = n >> 6, hs = n & 63;
    const float* W = (m == 0) ? Wq : ((m == 1) ? Wk : Wv);
    WallG[idx] = rna_tf32_f(W[k * HS + hs]);
}

// ============================================================================
// Kernel 1: QKV projection, 1xTF32, cp.async double-buffered.
// Epilogue: Q/K fp32 RNA-rounded row-major; V bf16 hi/lo transposed.
// ============================================================================
#define ASTRIDE 40
#define BSTRIDE 200
#define AOFFB 0
#define BOFFB 20480
#define QBUF  46080
#define QKV_SMEM (2 * QBUF)         // 92160 B

__global__ __launch_bounds__(256, 2)
void qkv_mma(const float* __restrict__ X)
{
    extern __shared__ char sm[];
    const int tid  = threadIdx.x;
    const int lane = tid & 31;
    const int w    = tid >> 5;
    const int m0   = (w >> 1) * 32;
    const int n0   = (w & 1) * 96;
    const int gid  = lane >> 2;
    const int tg   = lane & 3;
    const size_t row0 = (size_t)blockIdx.x * 128;
    const uint32_t sb = smem_u32(sm);

    auto stage = [&](int c, int buf) {
        const int k0 = c * 32;
        const uint32_t base = sb + buf * QBUF;
#pragma unroll
        for (int it = 0; it < 4; it++) {
            int i  = tid + 256 * it;
            int r  = i >> 3;
            int c4 = (i & 7) << 2;
            cp16(base + AOFFB + (uint32_t)(r * ASTRIDE + c4) * 4,
                 &X[(row0 + r) * CC + k0 + c4]);
        }
#pragma unroll
        for (int it = 0; it < 6; it++) {
            int i  = tid + 256 * it;
            int r  = i / 48;
            int c4 = (i % 48) << 2;
            cp16(base + BOFFB + (uint32_t)(r * BSTRIDE + c4) * 4,
                 &WallG[(size_t)(k0 + r) * 192 + c4]);
        }
        CP_COMMIT();
    };

    float acc[2][12][4] = {};

    stage(0, 0);
#pragma unroll 1
    for (int c = 0; c < 12; c++) {
        if (c < 11) { stage(c + 1, (c + 1) & 1); CP_WAIT1(); } else { CP_WAIT0(); }
        __syncthreads();
        const int buf = c & 1;
        const uint32_t* A = reinterpret_cast<const uint32_t*>(sm + buf * QBUF + AOFFB);
        const uint32_t* B = reinterpret_cast<const uint32_t*>(sm + buf * QBUF + BOFFB);

#pragma unroll
        for (int ks = 0; ks < 4; ks++) {
            const int kc = ks * 8 + tg;
            uint32_t a[2][4];
#pragma unroll
            for (int mt = 0; mt < 2; mt++) {
                const int r = m0 + mt * 16 + gid;
                a[mt][0] = rna_tf32(A[r * ASTRIDE + kc]);
                a[mt][1] = rna_tf32(A[(r + 8) * ASTRIDE + kc]);
                a[mt][2] = rna_tf32(A[r * ASTRIDE + kc + 4]);
                a[mt][3] = rna_tf32(A[(r + 8) * ASTRIDE + kc + 4]);
            }
#pragma unroll
            for (int nt = 0; nt < 12; nt++) {
                const int col = n0 + nt * 8 + gid;
                uint32_t b0 = B[kc * BSTRIDE + col];
                uint32_t b1 = B[(kc + 4) * BSTRIDE + col];
                mma16808t(acc[0][nt], a[0][0], a[0][1], a[0][2], a[0][3], b0, b1);
                mma16808t(acc[1][nt], a[1][0], a[1][1], a[1][2], a[1][3], b0, b1);
            }
        }
        __syncthreads();
    }

    // --- epilogue ---
#pragma unroll
    for (int nt = 0; nt < 12; nt++) {
        const int colg = n0 + nt * 8 + 2 * tg;
        const int mat  = colg >> 6;
        const int hs0  = colg & 63;
#pragma unroll
        for (int mt = 0; mt < 2; mt++) {
            const size_t rowA = row0 + m0 + mt * 16 + gid;
            const size_t rowB = rowA + 8;
            const float* cc = acc[mt][nt];
            if (mat == 2) {
                const size_t baseA = (rowA >> 8) * (size_t)(HS * TT) + (rowA & 255);
                const size_t baseB = (rowB >> 8) * (size_t)(HS * TT) + (rowB & 255);
#pragma unroll
                for (int e = 0; e < 4; e++) {
                    const float v = cc[e];
                    __nv_bfloat16 h = __float2bfloat16(v);
                    __nv_bfloat16 l = __float2bfloat16(v - __bfloat162float(h));
                    const size_t base = (e < 2) ? baseA : baseB;
                    const size_t off  = base + (size_t)(hs0 + (e & 1)) * TT;
                    VthG[off] = h;
                    VtlG[off] = l;
                }
            } else {
                float* dst = (mat == 0) ? QfG : KfG;
                *reinterpret_cast<float2*>(&dst[rowA * HS + hs0]) =
                    make_float2(rna_tf32_f(cc[0]), rna_tf32_f(cc[1]));
                *reinterpret_cast<float2*>(&dst[rowB * HS + hs0]) =
                    make_float2(rna_tf32_f(cc[2]), rna_tf32_f(cc[3]));
            }
        }
    }
}

// ============================================================================
// Kernel 2: FA2 attention. Scores = 1xTF32 (Q,K fp32 RNA); PV = 3-pass bf16.
// cp.async double-buffered 64-key chunks. Grid (2, 1024), 256 thr, 2 CTAs/SM.
// ============================================================================
#define KSTRIDE 68                          // K chunk stride in floats
#define KBYTES  (64 * KSTRIDE * 4)          // 17408
#define VP      72
#define VBYTES  (64 * VP * 2)               // 9216
#define ABUF    (KBYTES + 2 * VBYTES)       // 35840
#define ATTN_SMEM (2 * ABUF)                // 71680

__global__ __launch_bounds__(256, 2)
void attn_mma(float* __restrict__ out)
{
    extern __shared__ char sm[];
    const uint32_t sb = smem_u32(sm);
    const int half = blockIdx.x;
    const int b    = blockIdx.y;
    const int tid  = threadIdx.x;
    const int lane = tid & 31;
    const int w    = tid >> 5;
    const int gid  = lane >> 2;
    const int tg   = lane & 3;
    const int qb   = half * 128 + w * 16;

    auto stage = [&](int c, int buf) {
        const int kn0 = c * 64;
        const uint32_t base = sb + buf * ABUF;
        // K: 64 rows x 64 fp32
#pragma unroll
        for (int it = 0; it < 4; it++) {
            int i  = tid + 256 * it;       // 0..1023
            int r  = i >> 4;                // 0..63
            int c4 = (i & 15) << 2;         // 0..60
            cp16(base + (uint32_t)(r * KSTRIDE + c4) * 4,
                 &KfG[((size_t)b * TT + kn0 + r) * HS + c4]);
        }
        // Vh/Vl: 64 rows x 64 bf16 each
#pragma unroll
        for (int it = 0; it < 4; it++) {
            int i   = tid + 256 * it;      // 0..1023
            int arr = i >> 9;               // 0..1
            int rem = i & 511;
            int r   = rem >> 3;             // 0..63
            int c8  = (rem & 7) << 3;       // 0..56
            const __nv_bfloat16* src = arr
                ? &VtlG[((size_t)b * HS + r) * TT + kn0 + c8]
                : &VthG[((size_t)b * HS + r) * TT + kn0 + c8];
            cp16(base + KBYTES + arr * VBYTES + (uint32_t)(r * VP + c8) * 2, src);
        }
        CP_COMMIT();
    };

    // Q A-fragments (tf32, pre-rounded fp32 from global).
    uint32_t a[8][4];
    {
        const float* q0 = &QfG[((size_t)b * TT + qb + gid) * HS];
        const float* q1 = q0 + 8 * HS;
#pragma unroll
        for (int ks = 0; ks < 8; ks++) {
            a[ks][0] = __float_as_uint(q0[ks * 8 + tg]);
            a[ks][1] = __float_as_uint(q1[ks * 8 + tg]);
            a[ks][2] = __float_as_uint(q0[ks * 8 + tg + 4]);
            a[ks][3] = __float_as_uint(q1[ks * 8 + tg + 4]);
        }
    }

    float O[32];
#pragma unroll
    for (int i = 0; i < 32; i++) O[i] = 0.f;
    float mr0 = -1e30f, mr1 = -1e30f, l0 = 0.f, l1 = 0.f;

    const int nch = (half + 1) * 2;
    stage(0, 0);
#pragma unroll 1
    for (int c = 0; c < nch; c++) {
        if (c < nch - 1) { stage(c + 1, (c + 1) & 1); CP_WAIT1(); } else { CP_WAIT0(); }
        __syncthreads();
        const int kn0 = c * 64;
        const int buf = c & 1;
        const float* Ks = reinterpret_cast<const float*>(sm + buf * ABUF);
        const __nv_bfloat16* Vhs = reinterpret_cast<const __nv_bfloat16*>(sm + buf * ABUF + KBYTES);
        const __nv_bfloat16* Vls = reinterpret_cast<const __nv_bfloat16*>(sm + buf * ABUF + KBYTES + VBYTES);

        if (kn0 <= qb) {
            // ---- scores: S = Q K^T, single-pass tf32 ----
            float s[32];
#pragma unroll
            for (int i = 0; i < 32; i++) s[i] = 0.f;
#pragma unroll
            for (int nt = 0; nt < 8; nt++) {
                const float* kr = &Ks[(nt * 8 + gid) * KSTRIDE];
#pragma unroll
                for (int ks = 0; ks < 8; ks++) {
                    uint32_t b0 = __float_as_uint(kr[ks * 8 + tg]);
                    uint32_t b1 = __float_as_uint(kr[ks * 8 + tg + 4]);
                    mma16808t(&s[nt * 4], a[ks][0], a[ks][1], a[ks][2], a[ks][3], b0, b1);
                }
            }
#pragma unroll
            for (int i = 0; i < 32; i++) s[i] *= SCALE2;

            if (kn0 + 63 > qb) {
                const int r0 = qb + gid, r1 = qb + 8 + gid;
#pragma unroll
                for (int nt = 0; nt < 8; nt++) {
                    const int col = kn0 + nt * 8 + 2 * tg;
                    if (col     > r0) s[nt * 4 + 0] = -1e30f;
                    if (col + 1 > r0) s[nt * 4 + 1] = -1e30f;
                    if (col     > r1) s[nt * 4 + 2] = -1e30f;
                    if (col + 1 > r1) s[nt * 4 + 3] = -1e30f;
                }
            }
            // ---- online softmax (base-2) ----
            float c0m = -1e30f, c1m = -1e30f;
#pragma unroll
            for (int nt = 0; nt < 8; nt++) {
                c0m = fmaxf(c0m, fmaxf(s[nt * 4 + 0], s[nt * 4 + 1]));
                c1m = fmaxf(c1m, fmaxf(s[nt * 4 + 2], s[nt * 4 + 3]));
            }
            c0m = fmaxf(c0m, __shfl_xor_sync(0xffffffffu, c0m, 1));
            c0m = fmaxf(c0m, __shfl_xor_sync(0xffffffffu, c0m, 2));
            c1m = fmaxf(c1m, __shfl_xor_sync(0xffffffffu, c1m, 1));
            c1m = fmaxf(c1m, __shfl_xor_sync(0xffffffffu, c1m, 2));
            const float mn0 = fmaxf(mr0, c0m), mn1 = fmaxf(mr1, c1m);
            const float corr0 = fexp2f(mr0 - mn0), corr1 = fexp2f(mr1 - mn1);
            mr0 = mn0; mr1 = mn1;

            float sum0 = 0.f, sum1 = 0.f;
#pragma unroll
            for (int nt = 0; nt < 8; nt++) {
                float p0 = fexp2f(s[nt * 4 + 0] - mn0);
                float p1 = fexp2f(s[nt * 4 + 1] - mn0);
                float p2 = fexp2f(s[nt * 4 + 2] - mn1);
                float p3 = fexp2f(s[nt * 4 + 3] - mn1);
                s[nt * 4 + 0] = p0; s[nt * 4 + 1] = p1;
                s[nt * 4 + 2] = p2; s[nt * 4 + 3] = p3;
                sum0 += p0 + p1; sum1 += p2 + p3;
            }
            sum0 += __shfl_xor_sync(0xffffffffu, sum0, 1);
            sum0 += __shfl_xor_sync(0xffffffffu, sum0, 2);
            sum1 += __shfl_xor_sync(0xffffffffu, sum1, 1);
            sum1 += __shfl_xor_sync(0xffffffffu, sum1, 2);
            l0 = l0 * corr0 + sum0;
            l1 = l1 * corr1 + sum1;
#pragma unroll
            for (int hn = 0; hn < 8; hn++) {
                O[hn * 4 + 0] *= corr0; O[hn * 4 + 1] *= corr0;
                O[hn * 4 + 2] *= corr1; O[hn * 4 + 3] *= corr1;
            }
            // ---- PV: 3-pass bf16 (P register-reuse) ----
#pragma unroll
            for (int ks = 0; ks < 4; ks++) {
                uint32_t ph[4], pl[4];
                split2(s[(2 * ks) * 4 + 0],     s[(2 * ks) * 4 + 1],     ph[0], pl[0]);
                split2(s[(2 * ks) * 4 + 2],     s[(2 * ks) * 4 + 3],     ph[1], pl[1]);
                split2(s[(2 * ks + 1) * 4 + 0], s[(2 * ks + 1) * 4 + 1], ph[2], pl[2]);
                split2(s[(2 * ks + 1) * 4 + 2], s[(2 * ks + 1) * 4 + 3], ph[3], pl[3]);
#pragma unroll
                for (int hn = 0; hn < 8; hn++) {
                    const int vn = hn * 8 + gid;
                    uint32_t vh0 = *reinterpret_cast<const uint32_t*>(&Vhs[vn * VP + ks * 16 + 2 * tg]);
                    uint32_t vh1 = *reinterpret_cast<const uint32_t*>(&Vhs[vn * VP + ks * 16 + 2 * tg + 8]);
                    uint32_t vl0 = *reinterpret_cast<const uint32_t*>(&Vls[vn * VP + ks * 16 + 2 * tg]);
                    uint32_t vl1 = *reinterpret_cast<const uint32_t*>(&Vls[vn * VP + ks * 16 + 2 * tg + 8]);
                    float* o = &O[hn * 4];
                    mma16816(o[0], o[1], o[2], o[3], ph[0], ph[1], ph[2], ph[3], vh0, vh1);
                    mma16816(o[0], o[1], o[2], o[3], pl[0], pl[1], pl[2], pl[3], vh0, vh1);
                    mma16816(o[0], o[1], o[2], o[3], ph[0], ph[1], ph[2], ph[3], vl0, vl1);
                }
            }
        }
        __syncthreads();
    }

    const float i0 = 1.f / l0, i1 = 1.f / l1;
    float* o0 = out + ((size_t)b * TT + qb + gid) * HS;
    float* o1 = o0 + 8 * HS;
#pragma unroll
    for (int hn = 0; hn < 8; hn++) {
        *reinterpret_cast<float2*>(&o0[hn * 8 + 2 * tg]) =
            make_float2(O[hn * 4 + 0] * i0, O[hn * 4 + 1] * i0);
        *reinterpret_cast<float2*>(&o1[hn * 8 + 2 * tg]) =
            make_float2(O[hn * 4 + 2] * i1, O[hn * 4 + 3] * i1);
    }
}

// ============================================================================
extern "C" void kernel_launch(void* const* d_in, const int* in_sizes, int n_in,
                              void* d_out, int out_size)
{
    const float* x  = (const float*)d_in[0];
    const float* Wq = (const float*)d_in[1];
    const float* Wk = (const float*)d_in[2];
    const float* Wv = (const float*)d_in[3];
    float* out = (float*)d_out;

    (void)in_sizes; (void)n_in; (void)out_size;

    prep_w<<<(384 * 192 + 255) / 256, 256>>>(Wq, Wk, Wv);

    cudaFuncSetAttribute(qkv_mma, cudaFuncAttributeMaxDynamicSharedMemorySize, QKV_SMEM);
    qkv_mma<<<2048, 256, QKV_SMEM>>>(x);

    cudaFuncSetAttribute(attn_mma, cudaFuncAttributeMaxDynamicSharedMemorySize, ATTN_SMEM);
    dim3 agrid(2, BB);
    attn_mma<<<agrid, 256, ATTN_SMEM>>>(out);
}

// round 10
// speedup vs baseline: 1.0719x; 1.0020x over previous
#include <cuda_runtime.h>
#include <cuda_bf16.h>
#include <cstdint>

#define BB   1024
#define TT   256
#define CC   384
#define HS   64

// Scratch (device globals: allocation-free).
__device__ __align__(16) float QfG[BB * TT * HS];   // Q, tf32-RNA-rounded fp32
__device__ __align__(16) float KfG[BB * TT * HS];   // K, tf32-RNA-rounded fp32
__device__ __align__(16) __nv_bfloat16 VthG[BB * HS * TT], VtlG[BB * HS * TT]; // V^T hi/lo
__device__ __align__(16) float WallG[384 * 192];    // W concat (tf32-rounded), [k][n]

// ---------------- helpers ----------------
__device__ __forceinline__ uint32_t smem_u32(const void* p) {
    uint32_t a;
    asm("{ .reg .u64 t; cvta.to.shared.u64 t, %1; cvt.u32.u64 %0, t; }" : "=r"(a) : "l"(p));
    return a;
}
__device__ __forceinline__ void cp16(uint32_t dst, const void* src) {
    asm volatile("cp.async.ca.shared.global [%0], [%1], 16;" :: "r"(dst), "l"(src) : "memory");
}
#define CP_COMMIT() asm volatile("cp.async.commit_group;" ::: "memory")
#define CP_WAIT1()  asm volatile("cp.async.wait_group 1;" ::: "memory")
#define CP_WAIT0()  asm volatile("cp.async.wait_group 0;" ::: "memory")

__device__ __forceinline__ uint32_t rna_tf32(uint32_t x) {
    uint32_t r;
    asm("cvt.rna.tf32.f32 %0, %1;" : "=r"(r) : "r"(x));
    return r;
}
__device__ __forceinline__ float rna_tf32_f(float x) {
    float r;
    asm("cvt.rna.tf32.f32 %0, %1;" : "=f"(r) : "f"(x));
    return r;
}

// fp32 pair -> packed bf16 hi / lo pair.
__device__ __forceinline__ void split2(float a, float b, uint32_t& h, uint32_t& l) {
    __nv_bfloat162 hh = __floats2bfloat162_rn(a, b);
    float ra = a - __bfloat162float(hh.x);
    float rb = b - __bfloat162float(hh.y);
    __nv_bfloat162 ll = __floats2bfloat162_rn(ra, rb);
    h = *reinterpret_cast<uint32_t*>(&hh);
    l = *reinterpret_cast<uint32_t*>(&ll);
}

// exp2(x) for x <= 0, FMA pipe only.
__device__ __forceinline__ float fexp2f(float x) {
    x = fmaxf(x, -125.0f);
    float fi = floorf(x);
    float f = x - fi;
    float p = 0.0018775767f;
    p = fmaf(p, f, 0.0089893397f);
    p = fmaf(p, f, 0.055826318f);
    p = fmaf(p, f, 0.24015361f);
    p = fmaf(p, f, 0.69315308f);
    p = fmaf(p, f, 1.0f);
    return p * __int_as_float(((int)fi + 127) << 23);
}
#define SCALE2 0.18033688f   // 0.125 * log2(e)

// bf16 m16n8k16 MMA
__device__ __forceinline__ void mma16816(float& c0, float& c1, float& c2, float& c3,
                                         uint32_t a0, uint32_t a1, uint32_t a2, uint32_t a3,
                                         uint32_t b0, uint32_t b1) {
    asm volatile(
        "mma.sync.aligned.m16n8k16.row.col.f32.bf16.bf16.f32 "
        "{%0,%1,%2,%3}, {%4,%5,%6,%7}, {%8,%9}, {%0,%1,%2,%3};"
        : "+f"(c0), "+f"(c1), "+f"(c2), "+f"(c3)
        : "r"(a0), "r"(a1), "r"(a2), "r"(a3), "r"(b0), "r"(b1));
}

// tf32 m16n8k8 MMA
__device__ __forceinline__ void mma16808t(float* c,
                                          uint32_t a0, uint32_t a1, uint32_t a2, uint32_t a3,
                                          uint32_t b0, uint32_t b1) {
    asm volatile(
        "mma.sync.aligned.m16n8k8.row.col.f32.tf32.tf32.f32 "
        "{%0,%1,%2,%3}, {%4,%5,%6,%7}, {%8,%9}, {%0,%1,%2,%3};"
        : "+f"(c[0]), "+f"(c[1]), "+f"(c[2]), "+f"(c[3])
        : "r"(a0), "r"(a1), "r"(a2), "r"(a3), "r"(b0), "r"(b1));
}

// ============================================================================
// Kernel 0: concat W into fp32 [k=384][n=192], tf32-RNA-rounded.
// ============================================================================
__global__ void prep_w(const float* __restrict__ Wq,
                       const float* __restrict__ Wk,
                       const float* __restrict__ Wv)
{
    int idx = blockIdx.x * blockDim.x + threadIdx.x;
    if (idx >= 384 * 192) return;
    int k = idx / 192;
    int n = idx % 192;
    int m = n >> 6, hs = n & 63;
    const float* W = (m == 0) ? Wq : ((m == 1) ? Wk : Wv);
    WallG[idx] = rna_tf32_f(W[k * HS + hs]);
}

// ============================================================================
// Kernel 1: QKV projection, 1xTF32, cp.async double-buffered.
// Epilogue: Q/K fp32 RNA-rounded row-major; V bf16 hi/lo transposed.
// ============================================================================
#define ASTRIDE 40
#define BSTRIDE 200
#define AOFFB 0
#define BOFFB 20480
#define QBUF  46080
#define QKV_SMEM (2 * QBUF)         // 92160 B

__global__ __launch_bounds__(256, 2)
void qkv_mma(const float* __restrict__ X)
{
    extern __shared__ char sm[];
    const int tid  = threadIdx.x;
    const int lane = tid & 31;
    const int w    = tid >> 5;
    const int m0   = (w >> 1) * 32;
    const int n0   = (w & 1) * 96;
    const int gid  = lane >> 2;
    const int tg   = lane & 3;
    const size_t row0 = (size_t)blockIdx.x * 128;
    const uint32_t sb = smem_u32(sm);

    auto stage = [&](int c, int buf) {
        const int k0 = c * 32;
        const uint32_t base = sb + buf * QBUF;
#pragma unroll
        for (int it = 0; it < 4; it++) {
            int i  = tid + 256 * it;
            int r  = i >> 3;
            int c4 = (i & 7) << 2;
            cp16(base + AOFFB + (uint32_t)(r * ASTRIDE + c4) * 4,
                 &X[(row0 + r) * CC + k0 + c4]);
        }
#pragma unroll
        for (int it = 0; it < 6; it++) {
            int i  = tid + 256 * it;
            int r  = i / 48;
            int c4 = (i % 48) << 2;
            cp16(base + BOFFB + (uint32_t)(r * BSTRIDE + c4) * 4,
                 &WallG[(size_t)(k0 + r) * 192 + c4]);
        }
        CP_COMMIT();
    };

    float acc[2][12][4] = {};

    stage(0, 0);
#pragma unroll 1
    for (int c = 0; c < 12; c++) {
        if (c < 11) { stage(c + 1, (c + 1) & 1); CP_WAIT1(); } else { CP_WAIT0(); }
        __syncthreads();
        const int buf = c & 1;
        const uint32_t* A = reinterpret_cast<const uint32_t*>(sm + buf * QBUF + AOFFB);
        const uint32_t* B = reinterpret_cast<const uint32_t*>(sm + buf * QBUF + BOFFB);

#pragma unroll
        for (int ks = 0; ks < 4; ks++) {
            const int kc = ks * 8 + tg;
            uint32_t a[2][4];
#pragma unroll
            for (int mt = 0; mt < 2; mt++) {
                const int r = m0 + mt * 16 + gid;
                a[mt][0] = rna_tf32(A[r * ASTRIDE + kc]);
                a[mt][1] = rna_tf32(A[(r + 8) * ASTRIDE + kc]);
                a[mt][2] = rna_tf32(A[r * ASTRIDE + kc + 4]);
                a[mt][3] = rna_tf32(A[(r + 8) * ASTRIDE + kc + 4]);
            }
#pragma unroll
            for (int nt = 0; nt < 12; nt++) {
                const int col = n0 + nt * 8 + gid;
                uint32_t b0 = B[kc * BSTRIDE + col];
                uint32_t b1 = B[(kc + 4) * BSTRIDE + col];
                mma16808t(acc[0][nt], a[0][0], a[0][1], a[0][2], a[0][3], b0, b1);
                mma16808t(acc[1][nt], a[1][0], a[1][1], a[1][2], a[1][3], b0, b1);
            }
        }
        __syncthreads();
    }

    // --- epilogue ---
#pragma unroll
    for (int nt = 0; nt < 12; nt++) {
        const int colg = n0 + nt * 8 + 2 * tg;
        const int mat  = colg >> 6;
        const int hs0  = colg & 63;
#pragma unroll
        for (int mt = 0; mt < 2; mt++) {
            const size_t rowA = row0 + m0 + mt * 16 + gid;
            const size_t rowB = rowA + 8;
            const float* cc = acc[mt][nt];
            if (mat == 2) {
                const size_t baseA = (rowA >> 8) * (size_t)(HS * TT) + (rowA & 255);
                const size_t baseB = (rowB >> 8) * (size_t)(HS * TT) + (rowB & 255);
#pragma unroll
                for (int e = 0; e < 4; e++) {
                    const float v = cc[e];
                    __nv_bfloat16 h = __float2bfloat16(v);
                    __nv_bfloat16 l = __float2bfloat16(v - __bfloat162float(h));
                    const size_t base = (e < 2) ? baseA : baseB;
                    const size_t off  = base + (size_t)(hs0 + (e & 1)) * TT;
                    VthG[off] = h;
                    VtlG[off] = l;
                }
            } else {
                float* dst = (mat == 0) ? QfG : KfG;
                *reinterpret_cast<float2*>(&dst[rowA * HS + hs0]) =
                    make_float2(rna_tf32_f(cc[0]), rna_tf32_f(cc[1]));
                *reinterpret_cast<float2*>(&dst[rowB * HS + hs0]) =
                    make_float2(rna_tf32_f(cc[2]), rna_tf32_f(cc[3]));
            }
        }
    }
}

// ============================================================================
// Kernel 2: FA2 attention. Scores = 1xTF32; PV = 3-pass bf16.
// Diagonal-chunk trimming: per-tile warp-uniform guards skip fully-masked
// score n-tiles and PV k-groups. cp.async double-buffered 64-key chunks.
// Grid (2, 1024), 256 thr, 2 CTAs/SM.
// ============================================================================
#define KSTRIDE 68                          // K chunk stride in floats
#define KBYTES  (64 * KSTRIDE * 4)          // 17408
#define VP      72
#define VBYTES  (64 * VP * 2)               // 9216
#define ABUF    (KBYTES + 2 * VBYTES)       // 35840
#define ATTN_SMEM (2 * ABUF)                // 71680

__global__ __launch_bounds__(256, 2)
void attn_mma(float* __restrict__ out)
{
    extern __shared__ char sm[];
    const uint32_t sb = smem_u32(sm);
    const int half = blockIdx.x;
    const int b    = blockIdx.y;
    const int tid  = threadIdx.x;
    const int lane = tid & 31;
    const int w    = tid >> 5;
    const int gid  = lane >> 2;
    const int tg   = lane & 3;
    const int qb   = half * 128 + w * 16;
    const int qtop = qb + 15;                // last query row of this warp

    auto stage = [&](int c, int buf) {
        const int kn0 = c * 64;
        const uint32_t base = sb + buf * ABUF;
        // K: 64 rows x 64 fp32
#pragma unroll
        for (int it = 0; it < 4; it++) {
            int i  = tid + 256 * it;
            int r  = i >> 4;
            int c4 = (i & 15) << 2;
            cp16(base + (uint32_t)(r * KSTRIDE + c4) * 4,
                 &KfG[((size_t)b * TT + kn0 + r) * HS + c4]);
        }
        // Vh/Vl: 64 rows x 64 bf16 each
#pragma unroll
        for (int it = 0; it < 4; it++) {
            int i   = tid + 256 * it;
            int arr = i >> 9;
            int rem = i & 511;
            int r   = rem >> 3;
            int c8  = (rem & 7) << 3;
            const __nv_bfloat16* src = arr
                ? &VtlG[((size_t)b * HS + r) * TT + kn0 + c8]
                : &VthG[((size_t)b * HS + r) * TT + kn0 + c8];
            cp16(base + KBYTES + arr * VBYTES + (uint32_t)(r * VP + c8) * 2, src);
        }
        CP_COMMIT();
    };

    // Q A-fragments (tf32, pre-rounded fp32 from global).
    uint32_t a[8][4];
    {
        const float* q0 = &QfG[((size_t)b * TT + qb + gid) * HS];
        const float* q1 = q0 + 8 * HS;
#pragma unroll
        for (int ks = 0; ks < 8; ks++) {
            a[ks][0] = __float_as_uint(q0[ks * 8 + tg]);
            a[ks][1] = __float_as_uint(q1[ks * 8 + tg]);
            a[ks][2] = __float_as_uint(q0[ks * 8 + tg + 4]);
            a[ks][3] = __float_as_uint(q1[ks * 8 + tg + 4]);
        }
    }

    float O[32];
#pragma unroll
    for (int i = 0; i < 32; i++) O[i] = 0.f;
    float mr0 = -1e30f, mr1 = -1e30f, l0 = 0.f, l1 = 0.f;

    const int nch = (half + 1) * 2;
    stage(0, 0);
#pragma unroll 1
    for (int c = 0; c < nch; c++) {
        if (c < nch - 1) { stage(c + 1, (c + 1) & 1); CP_WAIT1(); } else { CP_WAIT0(); }
        __syncthreads();
        const int kn0 = c * 64;
        const int buf = c & 1;
        const float* Ks = reinterpret_cast<const float*>(sm + buf * ABUF);
        const __nv_bfloat16* Vhs = reinterpret_cast<const __nv_bfloat16*>(sm + buf * ABUF + KBYTES);
        const __nv_bfloat16* Vls = reinterpret_cast<const __nv_bfloat16*>(sm + buf * ABUF + KBYTES + VBYTES);

        if (kn0 <= qb) {
            // ---- scores: S = Q K^T, single-pass tf32, trimmed n-tiles ----
            float s[32];
#pragma unroll
            for (int nt = 0; nt < 8; nt++) {
                if (kn0 + nt * 8 <= qtop) {          // warp-uniform guard
                    s[nt * 4 + 0] = 0.f; s[nt * 4 + 1] = 0.f;
                    s[nt * 4 + 2] = 0.f; s[nt * 4 + 3] = 0.f;
                    const float* kr = &Ks[(nt * 8 + gid) * KSTRIDE];
#pragma unroll
                    for (int ks = 0; ks < 8; ks++) {
                        uint32_t b0 = __float_as_uint(kr[ks * 8 + tg]);
                        uint32_t b1 = __float_as_uint(kr[ks * 8 + tg + 4]);
                        mma16808t(&s[nt * 4], a[ks][0], a[ks][1], a[ks][2], a[ks][3], b0, b1);
                    }
                    s[nt * 4 + 0] *= SCALE2; s[nt * 4 + 1] *= SCALE2;
                    s[nt * 4 + 2] *= SCALE2; s[nt * 4 + 3] *= SCALE2;
                } else {
                    s[nt * 4 + 0] = -1e30f; s[nt * 4 + 1] = -1e30f;
                    s[nt * 4 + 2] = -1e30f; s[nt * 4 + 3] = -1e30f;
                }
            }

            if (kn0 + 63 > qb) {
                const int r0 = qb + gid, r1 = qb + 8 + gid;
#pragma unroll
                for (int nt = 0; nt < 8; nt++) {
                    const int col = kn0 + nt * 8 + 2 * tg;
                    if (col     > r0) s[nt * 4 + 0] = -1e30f;
                    if (col + 1 > r0) s[nt * 4 + 1] = -1e30f;
                    if (col     > r1) s[nt * 4 + 2] = -1e30f;
                    if (col + 1 > r1) s[nt * 4 + 3] = -1e30f;
                }
            }
            // ---- online softmax (base-2) ----
            float c0m = -1e30f, c1m = -1e30f;
#pragma unroll
            for (int nt = 0; nt < 8; nt++) {
                c0m = fmaxf(c0m, fmaxf(s[nt * 4 + 0], s[nt * 4 + 1]));
                c1m = fmaxf(c1m, fmaxf(s[nt * 4 + 2], s[nt * 4 + 3]));
            }
            c0m = fmaxf(c0m, __shfl_xor_sync(0xffffffffu, c0m, 1));
            c0m = fmaxf(c0m, __shfl_xor_sync(0xffffffffu, c0m, 2));
            c1m = fmaxf(c1m, __shfl_xor_sync(0xffffffffu, c1m, 1));
            c1m = fmaxf(c1m, __shfl_xor_sync(0xffffffffu, c1m, 2));
            const float mn0 = fmaxf(mr0, c0m), mn1 = fmaxf(mr1, c1m);
            const float corr0 = fexp2f(mr0 - mn0), corr1 = fexp2f(mr1 - mn1);
            mr0 = mn0; mr1 = mn1;

            float sum0 = 0.f, sum1 = 0.f;
#pragma unroll
            for (int nt = 0; nt < 8; nt++) {
                float p0 = fexp2f(s[nt * 4 + 0] - mn0);
                float p1 = fexp2f(s[nt * 4 + 1] - mn0);
                float p2 = fexp2f(s[nt * 4 + 2] - mn1);
                float p3 = fexp2f(s[nt * 4 + 3] - mn1);
                s[nt * 4 + 0] = p0; s[nt * 4 + 1] = p1;
                s[nt * 4 + 2] = p2; s[nt * 4 + 3] = p3;
                sum0 += p0 + p1; sum1 += p2 + p3;
            }
            sum0 += __shfl_xor_sync(0xffffffffu, sum0, 1);
            sum0 += __shfl_xor_sync(0xffffffffu, sum0, 2);
            sum1 += __shfl_xor_sync(0xffffffffu, sum1, 1);
            sum1 += __shfl_xor_sync(0xffffffffu, sum1, 2);
            l0 = l0 * corr0 + sum0;
            l1 = l1 * corr1 + sum1;
#pragma unroll
            for (int hn = 0; hn < 8; hn++) {
                O[hn * 4 + 0] *= corr0; O[hn * 4 + 1] *= corr0;
                O[hn * 4 + 2] *= corr1; O[hn * 4 + 3] *= corr1;
            }
            // ---- PV: 3-pass bf16, trimmed k-groups ----
#pragma unroll
            for (int ks = 0; ks < 4; ks++) {
                if (kn0 + ks * 16 <= qtop) {         // warp-uniform guard
                    uint32_t ph[4], pl[4];
                    split2(s[(2 * ks) * 4 + 0],     s[(2 * ks) * 4 + 1],     ph[0], pl[0]);
                    split2(s[(2 * ks) * 4 + 2],     s[(2 * ks) * 4 + 3],     ph[1], pl[1]);
                    split2(s[(2 * ks + 1) * 4 + 0], s[(2 * ks + 1) * 4 + 1], ph[2], pl[2]);
                    split2(s[(2 * ks + 1) * 4 + 2], s[(2 * ks + 1) * 4 + 3], ph[3], pl[3]);
#pragma unroll
                    for (int hn = 0; hn < 8; hn++) {
                        const int vn = hn * 8 + gid;
                        uint32_t vh0 = *reinterpret_cast<const uint32_t*>(&Vhs[vn * VP + ks * 16 + 2 * tg]);
                        uint32_t vh1 = *reinterpret_cast<const uint32_t*>(&Vhs[vn * VP + ks * 16 + 2 * tg + 8]);
                        uint32_t vl0 = *reinterpret_cast<const uint32_t*>(&Vls[vn * VP + ks * 16 + 2 * tg]);
                        uint32_t vl1 = *reinterpret_cast<const uint32_t*>(&Vls[vn * VP + ks * 16 + 2 * tg + 8]);
                        float* o = &O[hn * 4];
                        mma16816(o[0], o[1], o[2], o[3], ph[0], ph[1], ph[2], ph[3], vh0, vh1);
                        mma16816(o[0], o[1], o[2], o[3], pl[0], pl[1], pl[2], pl[3], vh0, vh1);
                        mma16816(o[0], o[1], o[2], o[3], ph[0], ph[1], ph[2], ph[3], vl0, vl1);
                    }
                }
            }
        }
        __syncthreads();
    }

    const float i0 = 1.f / l0, i1 = 1.f / l1;
    float* o0 = out + ((size_t)b * TT + qb + gid) * HS;
    float* o1 = o0 + 8 * HS;
#pragma unroll
    for (int hn = 0; hn < 8; hn++) {
        *reinterpret_cast<float2*>(&o0[hn * 8 + 2 * tg]) =
            make_float2(O[hn * 4 + 0] * i0, O[hn * 4 + 1] * i0);
        *reinterpret_cast<float2*>(&o1[hn * 8 + 2 * tg]) =
            make_float2(O[hn * 4 + 2] * i1, O[hn * 4 + 3] * i1);
    }
}

// ============================================================================
extern "C" void kernel_launch(void* const* d_in, const int* in_sizes, int n_in,
                              void* d_out, int out_size)
{
    const float* x  = (const float*)d_in[0];
    const float* Wq = (const float*)d_in[1];
    const float* Wk = (const float*)d_in[2];
    const float* Wv = (const float*)d_in[3];
    float* out = (float*)d_out;

    (void)in_sizes; (void)n_in; (void)out_size;

    prep_w<<<(384 * 192 + 255) / 256, 256>>>(Wq, Wk, Wv);

    cudaFuncSetAttribute(qkv_mma, cudaFuncAttributeMaxDynamicSharedMemorySize, QKV_SMEM);
    qkv_mma<<<2048, 256, QKV_SMEM>>>(x);

    cudaFuncSetAttribute(attn_mma, cudaFuncAttributeMaxDynamicSharedMemorySize, ATTN_SMEM);
    dim3 agrid(2, BB);
    attn_mma<<<agrid, 256, ATTN_SMEM>>>(out);
}

// round 11
// speedup vs baseline: 1.1276x; 1.0519x over previous
#include <cuda_runtime.h>
#include <cuda_bf16.h>
#include <cstdint>

#define BB   1024
#define TT   256
#define CC   384
#define HS   64

// Scratch (device globals: allocation-free).
__device__ __align__(16) float QfG[BB * TT * HS];   // Q, tf32-RNA-rounded fp32
__device__ __align__(16) float KfG[BB * TT * HS];   // K, tf32-RNA-rounded fp32
__device__ __align__(16) float VtfG[BB * HS * TT];  // V^T, tf32-RNA-rounded fp32 [b][hs][t]
__device__ __align__(16) float WallG[384 * 192];    // W concat (tf32-rounded), [k][n]

// ---------------- helpers ----------------
__device__ __forceinline__ uint32_t smem_u32(const void* p) {
    uint32_t a;
    asm("{ .reg .u64 t; cvta.to.shared.u64 t, %1; cvt.u32.u64 %0, t; }" : "=r"(a) : "l"(p));
    return a;
}
__device__ __forceinline__ void cp16(uint32_t dst, const void* src) {
    asm volatile("cp.async.ca.shared.global [%0], [%1], 16;" :: "r"(dst), "l"(src) : "memory");
}
#define CP_COMMIT() asm volatile("cp.async.commit_group;" ::: "memory")
#define CP_WAIT1()  asm volatile("cp.async.wait_group 1;" ::: "memory")
#define CP_WAIT0()  asm volatile("cp.async.wait_group 0;" ::: "memory")

__device__ __forceinline__ uint32_t rna_tf32(uint32_t x) {
    uint32_t r;
    asm("cvt.rna.tf32.f32 %0, %1;" : "=r"(r) : "r"(x));
    return r;
}
__device__ __forceinline__ float rna_tf32_f(float x) {
    float r;
    asm("cvt.rna.tf32.f32 %0, %1;" : "=f"(r) : "f"(x));
    return r;
}

// exp2(x) for x <= 0, FMA pipe only.
__device__ __forceinline__ float fexp2f(float x) {
    x = fmaxf(x, -125.0f);
    float fi = floorf(x);
    float f = x - fi;
    float p = 0.0018775767f;
    p = fmaf(p, f, 0.0089893397f);
    p = fmaf(p, f, 0.055826318f);
    p = fmaf(p, f, 0.24015361f);
    p = fmaf(p, f, 0.69315308f);
    p = fmaf(p, f, 1.0f);
    return p * __int_as_float(((int)fi + 127) << 23);
}
#define SCALE2 0.18033688f   // 0.125 * log2(e)

// tf32 m16n8k8 MMA
__device__ __forceinline__ void mma16808t(float* c,
                                          uint32_t a0, uint32_t a1, uint32_t a2, uint32_t a3,
                                          uint32_t b0, uint32_t b1) {
    asm volatile(
        "mma.sync.aligned.m16n8k8.row.col.f32.tf32.tf32.f32 "
        "{%0,%1,%2,%3}, {%4,%5,%6,%7}, {%8,%9}, {%0,%1,%2,%3};"
        : "+f"(c[0]), "+f"(c[1]), "+f"(c[2]), "+f"(c[3])
        : "r"(a0), "r"(a1), "r"(a2), "r"(a3), "r"(b0), "r"(b1));
}

// ============================================================================
// Kernel 0: concat W into fp32 [k=384][n=192], tf32-RNA-rounded.
// ============================================================================
__global__ void prep_w(const float* __restrict__ Wq,
                       const float* __restrict__ Wk,
                       const float* __restrict__ Wv)
{
    int idx = blockIdx.x * blockDim.x + threadIdx.x;
    if (idx >= 384 * 192) return;
    int k = idx / 192;
    int n = idx % 192;
    int m = n >> 6, hs = n & 63;
    const float* W = (m == 0) ? Wq : ((m == 1) ? Wk : Wv);
    WallG[idx] = rna_tf32_f(W[k * HS + hs]);
}

// ============================================================================
// Kernel 1: QKV projection, 1xTF32, cp.async double-buffered.
// Epilogue: Q/K fp32 RNA-rounded row-major; V fp32 RNA-rounded transposed.
// ============================================================================
#define ASTRIDE 40
#define BSTRIDE 200
#define AOFFB 0
#define BOFFB 20480
#define QBUF  46080
#define QKV_SMEM (2 * QBUF)         // 92160 B

__global__ __launch_bounds__(256, 2)
void qkv_mma(const float* __restrict__ X)
{
    extern __shared__ char sm[];
    const int tid  = threadIdx.x;
    const int lane = tid & 31;
    const int w    = tid >> 5;
    const int m0   = (w >> 1) * 32;
    const int n0   = (w & 1) * 96;
    const int gid  = lane >> 2;
    const int tg   = lane & 3;
    const size_t row0 = (size_t)blockIdx.x * 128;
    const uint32_t sb = smem_u32(sm);

    auto stage = [&](int c, int buf) {
        const int k0 = c * 32;
        const uint32_t base = sb + buf * QBUF;
#pragma unroll
        for (int it = 0; it < 4; it++) {
            int i  = tid + 256 * it;
            int r  = i >> 3;
            int c4 = (i & 7) << 2;
            cp16(base + AOFFB + (uint32_t)(r * ASTRIDE + c4) * 4,
                 &X[(row0 + r) * CC + k0 + c4]);
        }
#pragma unroll
        for (int it = 0; it < 6; it++) {
            int i  = tid + 256 * it;
            int r  = i / 48;
            int c4 = (i % 48) << 2;
            cp16(base + BOFFB + (uint32_t)(r * BSTRIDE + c4) * 4,
                 &WallG[(size_t)(k0 + r) * 192 + c4]);
        }
        CP_COMMIT();
    };

    float acc[2][12][4] = {};

    stage(0, 0);
#pragma unroll 1
    for (int c = 0; c < 12; c++) {
        if (c < 11) { stage(c + 1, (c + 1) & 1); CP_WAIT1(); } else { CP_WAIT0(); }
        __syncthreads();
        const int buf = c & 1;
        const uint32_t* A = reinterpret_cast<const uint32_t*>(sm + buf * QBUF + AOFFB);
        const uint32_t* B = reinterpret_cast<const uint32_t*>(sm + buf * QBUF + BOFFB);

#pragma unroll
        for (int ks = 0; ks < 4; ks++) {
            const int kc = ks * 8 + tg;
            uint32_t a[2][4];
#pragma unroll
            for (int mt = 0; mt < 2; mt++) {
                const int r = m0 + mt * 16 + gid;
                a[mt][0] = rna_tf32(A[r * ASTRIDE + kc]);
                a[mt][1] = rna_tf32(A[(r + 8) * ASTRIDE + kc]);
                a[mt][2] = rna_tf32(A[r * ASTRIDE + kc + 4]);
                a[mt][3] = rna_tf32(A[(r + 8) * ASTRIDE + kc + 4]);
            }
#pragma unroll
            for (int nt = 0; nt < 12; nt++) {
                const int col = n0 + nt * 8 + gid;
                uint32_t b0 = B[kc * BSTRIDE + col];
                uint32_t b1 = B[(kc + 4) * BSTRIDE + col];
                mma16808t(acc[0][nt], a[0][0], a[0][1], a[0][2], a[0][3], b0, b1);
                mma16808t(acc[1][nt], a[1][0], a[1][1], a[1][2], a[1][3], b0, b1);
            }
        }
        __syncthreads();
    }

    // --- epilogue ---
#pragma unroll
    for (int nt = 0; nt < 12; nt++) {
        const int colg = n0 + nt * 8 + 2 * tg;
        const int mat  = colg >> 6;
        const int hs0  = colg & 63;
#pragma unroll
        for (int mt = 0; mt < 2; mt++) {
            const size_t rowA = row0 + m0 + mt * 16 + gid;
            const size_t rowB = rowA + 8;
            const float* cc = acc[mt][nt];
            if (mat == 2) {
                const size_t baseA = (rowA >> 8) * (size_t)(HS * TT) + (rowA & 255);
                const size_t baseB = (rowB >> 8) * (size_t)(HS * TT) + (rowB & 255);
                VtfG[baseA + (size_t)hs0 * TT]       = rna_tf32_f(cc[0]);
                VtfG[baseA + (size_t)(hs0 + 1) * TT] = rna_tf32_f(cc[1]);
                VtfG[baseB + (size_t)hs0 * TT]       = rna_tf32_f(cc[2]);
                VtfG[baseB + (size_t)(hs0 + 1) * TT] = rna_tf32_f(cc[3]);
            } else {
                float* dst = (mat == 0) ? QfG : KfG;
                *reinterpret_cast<float2*>(&dst[rowA * HS + hs0]) =
                    make_float2(rna_tf32_f(cc[0]), rna_tf32_f(cc[1]));
                *reinterpret_cast<float2*>(&dst[rowB * HS + hs0]) =
                    make_float2(rna_tf32_f(cc[2]), rna_tf32_f(cc[3]));
            }
        }
    }
}

// ============================================================================
// Kernel 2: FA2 attention, all-tf32 MMAs (scores AND PV).
// P C-fragments are shuffled into tf32 A-fragment layout (quad shfl).
// Straight-line path for non-diagonal chunks; guarded path only on the
// diagonal chunk. cp.async double-buffered 64-key chunks.
// Grid (2, 1024), 256 thr, 2 CTAs/SM.
// ============================================================================
#define KSTRIDE 68                          // K / V chunk stride in floats
#define KBYTES  (64 * KSTRIDE * 4)          // 17408
#define ABUF    (2 * KBYTES)                // K | Vt   -> 34816
#define ATTN_SMEM (2 * ABUF)                // 69632

// ---- one 8-key score n-tile (tf32) ----
#define SCORE_TILE(nt) do {                                                  \
    float cc[4] = {0.f, 0.f, 0.f, 0.f};                                      \
    const float* kr = &Ks[((nt) * 8 + gid) * KSTRIDE];                       \
    _Pragma("unroll")                                                        \
    for (int ks = 0; ks < 8; ks++) {                                         \
        uint32_t b0 = __float_as_uint(kr[ks * 8 + tg]);                      \
        uint32_t b1 = __float_as_uint(kr[ks * 8 + tg + 4]);                  \
        mma16808t(cc, a[ks][0], a[ks][1], a[ks][2], a[ks][3], b0, b1);       \
    }                                                                        \
    s[(nt) * 4 + 0] = cc[0] * SCALE2; s[(nt) * 4 + 1] = cc[1] * SCALE2;      \
    s[(nt) * 4 + 2] = cc[2] * SCALE2; s[(nt) * 4 + 3] = cc[3] * SCALE2;      \
} while (0)

#define SCORE_MASK2(nt) do {                                                 \
    s[(nt) * 4 + 0] = -1e30f; s[(nt) * 4 + 1] = -1e30f;                      \
    s[(nt) * 4 + 2] = -1e30f; s[(nt) * 4 + 3] = -1e30f;                      \
    s[(nt) * 4 + 4] = -1e30f; s[(nt) * 4 + 5] = -1e30f;                      \
    s[(nt) * 4 + 6] = -1e30f; s[(nt) * 4 + 7] = -1e30f;                      \
} while (0)

// ---- one 8-key PV group (tf32): shuffle P into A-fragment layout, 8 MMAs --
#define PV_GROUP(g) do {                                                     \
    const int lb   = lane & ~3;                                              \
    const int srcA = lb | (tg >> 1);                                         \
    const int srcB = lb | 2 | (tg >> 1);                                     \
    float v00 = __shfl_sync(0xffffffffu, s[(g) * 4 + 0], srcA);              \
    float v01 = __shfl_sync(0xffffffffu, s[(g) * 4 + 1], srcA);              \
    float v10 = __shfl_sync(0xffffffffu, s[(g) * 4 + 2], srcA);              \
    float v11 = __shfl_sync(0xffffffffu, s[(g) * 4 + 3], srcA);              \
    float w00 = __shfl_sync(0xffffffffu, s[(g) * 4 + 0], srcB);              \
    float w01 = __shfl_sync(0xffffffffu, s[(g) * 4 + 1], srcB);              \
    float w10 = __shfl_sync(0xffffffffu, s[(g) * 4 + 2], srcB);              \
    float w11 = __shfl_sync(0xffffffffu, s[(g) * 4 + 3], srcB);              \
    const bool podd = (tg & 1);                                              \
    uint32_t pa0 = __float_as_uint(podd ? v01 : v00);                        \
    uint32_t pa1 = __float_as_uint(podd ? v11 : v10);                        \
    uint32_t pa2 = __float_as_uint(podd ? w01 : w00);                        \
    uint32_t pa3 = __float_as_uint(podd ? w11 : w10);                        \
    _Pragma("unroll")                                                        \
    for (int hn = 0; hn < 8; hn++) {                                         \
        const float* vr = &Vs[(hn * 8 + gid) * KSTRIDE + (g) * 8];           \
        uint32_t b0 = __float_as_uint(vr[tg]);                               \
        uint32_t b1 = __float_as_uint(vr[tg + 4]);                           \
        mma16808t(&O[hn * 4], pa0, pa1, pa2, pa3, b0, b1);                   \
    }                                                                        \
} while (0)

__global__ __launch_bounds__(256, 2)
void attn_mma(float* __restrict__ out)
{
    extern __shared__ char sm[];
    const uint32_t sb = smem_u32(sm);
    const int half = blockIdx.x;
    const int b    = blockIdx.y;
    const int tid  = threadIdx.x;
    const int lane = tid & 31;
    const int w    = tid >> 5;
    const int gid  = lane >> 2;
    const int tg   = lane & 3;
    const int qb   = half * 128 + w * 16;

    auto stage = [&](int c, int buf) {
        const int kn0 = c * 64;
        const uint32_t base = sb + buf * ABUF;
        // K: 64 key-rows x 64 fp32
#pragma unroll
        for (int it = 0; it < 4; it++) {
            int i  = tid + 256 * it;
            int r  = i >> 4;
            int c4 = (i & 15) << 2;
            cp16(base + (uint32_t)(r * KSTRIDE + c4) * 4,
                 &KfG[((size_t)b * TT + kn0 + r) * HS + c4]);
        }
        // Vt: 64 hs-rows x 64 keys fp32
#pragma unroll
        for (int it = 0; it < 4; it++) {
            int i  = tid + 256 * it;
            int r  = i >> 4;
            int c4 = (i & 15) << 2;
            cp16(base + KBYTES + (uint32_t)(r * KSTRIDE + c4) * 4,
                 &VtfG[((size_t)b * HS + r) * TT + kn0 + c4]);
        }
        CP_COMMIT();
    };

    // Q A-fragments (tf32, pre-rounded fp32 from global).
    uint32_t a[8][4];
    {
        const float* q0 = &QfG[((size_t)b * TT + qb + gid) * HS];
        const float* q1 = q0 + 8 * HS;
#pragma unroll
        for (int ks = 0; ks < 8; ks++) {
            a[ks][0] = __float_as_uint(q0[ks * 8 + tg]);
            a[ks][1] = __float_as_uint(q1[ks * 8 + tg]);
            a[ks][2] = __float_as_uint(q0[ks * 8 + tg + 4]);
            a[ks][3] = __float_as_uint(q1[ks * 8 + tg + 4]);
        }
    }

    float O[32];
#pragma unroll
    for (int i = 0; i < 32; i++) O[i] = 0.f;
    float mr0 = -1e30f, mr1 = -1e30f, l0 = 0.f, l1 = 0.f;

    const int nch = (half + 1) * 2;
    stage(0, 0);
#pragma unroll 1
    for (int c = 0; c < nch; c++) {
        if (c < nch - 1) { stage(c + 1, (c + 1) & 1); CP_WAIT1(); } else { CP_WAIT0(); }
        __syncthreads();
        const int kn0 = c * 64;
        const int buf = c & 1;
        const float* Ks = reinterpret_cast<const float*>(sm + buf * ABUF);
        const float* Vs = reinterpret_cast<const float*>(sm + buf * ABUF + KBYTES);

        if (kn0 <= qb) {
            const bool diag = (kn0 + 63 > qb);
            const int ntmax = diag ? (((qb + 15 - kn0) >> 3) + 1) : 8;  // 2,4,6,8
            float s[32];

            // ---- scores ----
            if (!diag) {
                SCORE_TILE(0); SCORE_TILE(1); SCORE_TILE(2); SCORE_TILE(3);
                SCORE_TILE(4); SCORE_TILE(5); SCORE_TILE(6); SCORE_TILE(7);
            } else {
                SCORE_TILE(0); SCORE_TILE(1);
                if (ntmax > 2) { SCORE_TILE(2); SCORE_TILE(3); } else { SCORE_MASK2(2); }
                if (ntmax > 4) { SCORE_TILE(4); SCORE_TILE(5); } else { SCORE_MASK2(4); }
                if (ntmax > 6) { SCORE_TILE(6); SCORE_TILE(7); } else { SCORE_MASK2(6); }
                // per-element causal mask on the diagonal chunk
                const int r0 = qb + gid, r1 = qb + 8 + gid;
#pragma unroll
                for (int nt = 0; nt < 8; nt++) {
                    const int col = kn0 + nt * 8 + 2 * tg;
                    if (col     > r0) s[nt * 4 + 0] = -1e30f;
                    if (col + 1 > r0) s[nt * 4 + 1] = -1e30f;
                    if (col     > r1) s[nt * 4 + 2] = -1e30f;
                    if (col + 1 > r1) s[nt * 4 + 3] = -1e30f;
                }
            }

            // ---- online softmax (base-2) ----
            float c0m = -1e30f, c1m = -1e30f;
#pragma unroll
            for (int nt = 0; nt < 8; nt++) {
                c0m = fmaxf(c0m, fmaxf(s[nt * 4 + 0], s[nt * 4 + 1]));
                c1m = fmaxf(c1m, fmaxf(s[nt * 4 + 2], s[nt * 4 + 3]));
            }
            c0m = fmaxf(c0m, __shfl_xor_sync(0xffffffffu, c0m, 1));
            c0m = fmaxf(c0m, __shfl_xor_sync(0xffffffffu, c0m, 2));
            c1m = fmaxf(c1m, __shfl_xor_sync(0xffffffffu, c1m, 1));
            c1m = fmaxf(c1m, __shfl_xor_sync(0xffffffffu, c1m, 2));
            const float mn0 = fmaxf(mr0, c0m), mn1 = fmaxf(mr1, c1m);
            const float corr0 = fexp2f(mr0 - mn0), corr1 = fexp2f(mr1 - mn1);
            mr0 = mn0; mr1 = mn1;

            float sum0 = 0.f, sum1 = 0.f;
#pragma unroll
            for (int nt = 0; nt < 8; nt++) {
                float p0 = fexp2f(s[nt * 4 + 0] - mn0);
                float p1 = fexp2f(s[nt * 4 + 1] - mn0);
                float p2 = fexp2f(s[nt * 4 + 2] - mn1);
                float p3 = fexp2f(s[nt * 4 + 3] - mn1);
                s[nt * 4 + 0] = p0; s[nt * 4 + 1] = p1;
                s[nt * 4 + 2] = p2; s[nt * 4 + 3] = p3;
                sum0 += p0 + p1; sum1 += p2 + p3;
            }
            sum0 += __shfl_xor_sync(0xffffffffu, sum0, 1);
            sum0 += __shfl_xor_sync(0xffffffffu, sum0, 2);
            sum1 += __shfl_xor_sync(0xffffffffu, sum1, 1);
            sum1 += __shfl_xor_sync(0xffffffffu, sum1, 2);
            l0 = l0 * corr0 + sum0;
            l1 = l1 * corr1 + sum1;
#pragma unroll
            for (int hn = 0; hn < 8; hn++) {
                O[hn * 4 + 0] *= corr0; O[hn * 4 + 1] *= corr0;
                O[hn * 4 + 2] *= corr1; O[hn * 4 + 3] *= corr1;
            }

            // ---- PV (tf32, P via quad-shuffle transpose) ----
            if (!diag) {
                PV_GROUP(0); PV_GROUP(1); PV_GROUP(2); PV_GROUP(3);
                PV_GROUP(4); PV_GROUP(5); PV_GROUP(6); PV_GROUP(7);
            } else {
                PV_GROUP(0); PV_GROUP(1);
                if (ntmax > 2) { PV_GROUP(2); PV_GROUP(3); }
                if (ntmax > 4) { PV_GROUP(4); PV_GROUP(5); }
                if (ntmax > 6) { PV_GROUP(6); PV_GROUP(7); }
            }
        }
        __syncthreads();
    }

    const float i0 = 1.f / l0, i1 = 1.f / l1;
    float* o0 = out + ((size_t)b * TT + qb + gid) * HS;
    float* o1 = o0 + 8 * HS;
#pragma unroll
    for (int hn = 0; hn < 8; hn++) {
        *reinterpret_cast<float2*>(&o0[hn * 8 + 2 * tg]) =
            make_float2(O[hn * 4 + 0] * i0, O[hn * 4 + 1] * i0);
        *reinterpret_cast<float2*>(&o1[hn * 8 + 2 * tg]) =
            make_float2(O[hn * 4 + 2] * i1, O[hn * 4 + 3] * i1);
    }
}

// ============================================================================
extern "C" void kernel_launch(void* const* d_in, const int* in_sizes, int n_in,
                              void* d_out, int out_size)
{
    const float* x  = (const float*)d_in[0];
    const float* Wq = (const float*)d_in[1];
    const float* Wk = (const float*)d_in[2];
    const float* Wv = (const float*)d_in[3];
    float* out = (float*)d_out;

    (void)in_sizes; (void)n_in; (void)out_size;

    prep_w<<<(384 * 192 + 255) / 256, 256>>>(Wq, Wk, Wv);

    cudaFuncSetAttribute(qkv_mma, cudaFuncAttributeMaxDynamicSharedMemorySize, QKV_SMEM);
    qkv_mma<<<2048, 256, QKV_SMEM>>>(x);

    cudaFuncSetAttribute(attn_mma, cudaFuncAttributeMaxDynamicSharedMemorySize, ATTN_SMEM);
    dim3 agrid(2, BB);
    attn_mma<<<agrid, 256, ATTN_SMEM>>>(out);
}

// round 12
// speedup vs baseline: 1.1615x; 1.0301x over previous
#include <cuda_runtime.h>
#include <cuda_bf16.h>
#include <cstdint>

#define BB   1024
#define TT   256
#define CC   384
#define HS   64

// Scratch (device globals: allocation-free).
__device__ __align__(16) float QfG[BB * TT * HS];   // Q * SCALE2, tf32-RNA-rounded fp32
__device__ __align__(16) float KfG[BB * TT * HS];   // K, tf32-RNA-rounded fp32
__device__ __align__(16) float VtfG[BB * HS * TT];  // V^T, tf32-RNA-rounded fp32 [b][hs][t]
__device__ __align__(16) float WallG[384 * 192];    // W concat (tf32-rounded), [k][n]

// ---------------- helpers ----------------
__device__ __forceinline__ uint32_t smem_u32(const void* p) {
    uint32_t a;
    asm("{ .reg .u64 t; cvta.to.shared.u64 t, %1; cvt.u32.u64 %0, t; }" : "=r"(a) : "l"(p));
    return a;
}
__device__ __forceinline__ void cp16(uint32_t dst, const void* src) {
    asm volatile("cp.async.ca.shared.global [%0], [%1], 16;" :: "r"(dst), "l"(src) : "memory");
}
#define CP_COMMIT() asm volatile("cp.async.commit_group;" ::: "memory")
#define CP_WAIT1()  asm volatile("cp.async.wait_group 1;" ::: "memory")
#define CP_WAIT0()  asm volatile("cp.async.wait_group 0;" ::: "memory")

__device__ __forceinline__ uint32_t rna_tf32(uint32_t x) {
    uint32_t r;
    asm("cvt.rna.tf32.f32 %0, %1;" : "=r"(r) : "r"(x));
    return r;
}
__device__ __forceinline__ float rna_tf32_f(float x) {
    float r;
    asm("cvt.rna.tf32.f32 %0, %1;" : "=f"(r) : "f"(x));
    return r;
}

// MUFU exp2 (single issue slot; ~2^-22 rel err; flushes huge-negative to 0)
__device__ __forceinline__ float ex2f(float x) {
    float r;
    asm("ex2.approx.f32 %0, %1;" : "=f"(r) : "f"(x));
    return r;
}
#define SCALE2 0.18033688f   // 0.125 * log2(e)

// tf32 m16n8k8 MMA
__device__ __forceinline__ void mma16808t(float* c,
                                          uint32_t a0, uint32_t a1, uint32_t a2, uint32_t a3,
                                          uint32_t b0, uint32_t b1) {
    asm volatile(
        "mma.sync.aligned.m16n8k8.row.col.f32.tf32.tf32.f32 "
        "{%0,%1,%2,%3}, {%4,%5,%6,%7}, {%8,%9}, {%0,%1,%2,%3};"
        : "+f"(c[0]), "+f"(c[1]), "+f"(c[2]), "+f"(c[3])
        : "r"(a0), "r"(a1), "r"(a2), "r"(a3), "r"(b0), "r"(b1));
}

// ============================================================================
// Kernel 0: concat W into fp32 [k=384][n=192], tf32-RNA-rounded.
// ============================================================================
__global__ void prep_w(const float* __restrict__ Wq,
                       const float* __restrict__ Wk,
                       const float* __restrict__ Wv)
{
    int idx = blockIdx.x * blockDim.x + threadIdx.x;
    if (idx >= 384 * 192) return;
    int k = idx / 192;
    int n = idx % 192;
    int m = n >> 6, hs = n & 63;
    const float* W = (m == 0) ? Wq : ((m == 1) ? Wk : Wv);
    WallG[idx] = rna_tf32_f(W[k * HS + hs]);
}

// ============================================================================
// Kernel 1: QKV projection, 1xTF32, cp.async double-buffered.
// Epilogue: Q (pre-scaled by SCALE2) / K fp32 RNA row-major; V fp32 RNA ^T.
// ============================================================================
#define ASTRIDE 40
#define BSTRIDE 200
#define AOFFB 0
#define BOFFB 20480
#define QBUF  46080
#define QKV_SMEM (2 * QBUF)         // 92160 B

__global__ __launch_bounds__(256, 2)
void qkv_mma(const float* __restrict__ X)
{
    extern __shared__ char sm[];
    const int tid  = threadIdx.x;
    const int lane = tid & 31;
    const int w    = tid >> 5;
    const int m0   = (w >> 1) * 32;
    const int n0   = (w & 1) * 96;
    const int gid  = lane >> 2;
    const int tg   = lane & 3;
    const size_t row0 = (size_t)blockIdx.x * 128;
    const uint32_t sb = smem_u32(sm);

    auto stage = [&](int c, int buf) {
        const int k0 = c * 32;
        const uint32_t base = sb + buf * QBUF;
#pragma unroll
        for (int it = 0; it < 4; it++) {
            int i  = tid + 256 * it;
            int r  = i >> 3;
            int c4 = (i & 7) << 2;
            cp16(base + AOFFB + (uint32_t)(r * ASTRIDE + c4) * 4,
                 &X[(row0 + r) * CC + k0 + c4]);
        }
#pragma unroll
        for (int it = 0; it < 6; it++) {
            int i  = tid + 256 * it;
            int r  = i / 48;
            int c4 = (i % 48) << 2;
            cp16(base + BOFFB + (uint32_t)(r * BSTRIDE + c4) * 4,
                 &WallG[(size_t)(k0 + r) * 192 + c4]);
        }
        CP_COMMIT();
    };

    float acc[2][12][4] = {};

    stage(0, 0);
#pragma unroll 1
    for (int c = 0; c < 12; c++) {
        if (c < 11) { stage(c + 1, (c + 1) & 1); CP_WAIT1(); } else { CP_WAIT0(); }
        __syncthreads();
        const int buf = c & 1;
        const uint32_t* A = reinterpret_cast<const uint32_t*>(sm + buf * QBUF + AOFFB);
        const uint32_t* B = reinterpret_cast<const uint32_t*>(sm + buf * QBUF + BOFFB);

#pragma unroll
        for (int ks = 0; ks < 4; ks++) {
            const int kc = ks * 8 + tg;
            uint32_t a[2][4];
#pragma unroll
            for (int mt = 0; mt < 2; mt++) {
                const int r = m0 + mt * 16 + gid;
                a[mt][0] = rna_tf32(A[r * ASTRIDE + kc]);
                a[mt][1] = rna_tf32(A[(r + 8) * ASTRIDE + kc]);
                a[mt][2] = rna_tf32(A[r * ASTRIDE + kc + 4]);
                a[mt][3] = rna_tf32(A[(r + 8) * ASTRIDE + kc + 4]);
            }
#pragma unroll
            for (int nt = 0; nt < 12; nt++) {
                const int col = n0 + nt * 8 + gid;
                uint32_t b0 = B[kc * BSTRIDE + col];
                uint32_t b1 = B[(kc + 4) * BSTRIDE + col];
                mma16808t(acc[0][nt], a[0][0], a[0][1], a[0][2], a[0][3], b0, b1);
                mma16808t(acc[1][nt], a[1][0], a[1][1], a[1][2], a[1][3], b0, b1);
            }
        }
        __syncthreads();
    }

    // --- epilogue ---
#pragma unroll
    for (int nt = 0; nt < 12; nt++) {
        const int colg = n0 + nt * 8 + 2 * tg;
        const int mat  = colg >> 6;
        const int hs0  = colg & 63;
#pragma unroll
        for (int mt = 0; mt < 2; mt++) {
            const size_t rowA = row0 + m0 + mt * 16 + gid;
            const size_t rowB = rowA + 8;
            const float* cc = acc[mt][nt];
            if (mat == 2) {
                const size_t baseA = (rowA >> 8) * (size_t)(HS * TT) + (rowA & 255);
                const size_t baseB = (rowB >> 8) * (size_t)(HS * TT) + (rowB & 255);
                VtfG[baseA + (size_t)hs0 * TT]       = rna_tf32_f(cc[0]);
                VtfG[baseA + (size_t)(hs0 + 1) * TT] = rna_tf32_f(cc[1]);
                VtfG[baseB + (size_t)hs0 * TT]       = rna_tf32_f(cc[2]);
                VtfG[baseB + (size_t)(hs0 + 1) * TT] = rna_tf32_f(cc[3]);
            } else if (mat == 0) {
                // Q: fold softmax scale (base-2) in before tf32 rounding
                *reinterpret_cast<float2*>(&QfG[rowA * HS + hs0]) =
                    make_float2(rna_tf32_f(cc[0] * SCALE2), rna_tf32_f(cc[1] * SCALE2));
                *reinterpret_cast<float2*>(&QfG[rowB * HS + hs0]) =
                    make_float2(rna_tf32_f(cc[2] * SCALE2), rna_tf32_f(cc[3] * SCALE2));
            } else {
                *reinterpret_cast<float2*>(&KfG[rowA * HS + hs0]) =
                    make_float2(rna_tf32_f(cc[0]), rna_tf32_f(cc[1]));
                *reinterpret_cast<float2*>(&KfG[rowB * HS + hs0]) =
                    make_float2(rna_tf32_f(cc[2]), rna_tf32_f(cc[3]));
            }
        }
    }
}

// ============================================================================
// Kernel 2: FA2 attention, all-tf32 MMAs, MUFU exp2 softmax.
// Grid (2, 1024), 256 thr, 2 CTAs/SM, cp.async double-buffered 64-key chunks.
// ============================================================================
#define KSTRIDE 68                          // K / V chunk stride in floats
#define KBYTES  (64 * KSTRIDE * 4)          // 17408
#define ABUF    (2 * KBYTES)                // K | Vt   -> 34816
#define ATTN_SMEM (2 * ABUF)                // 69632

// ---- one 8-key score n-tile (tf32); Q is pre-scaled, no epilogue mul ----
#define SCORE_TILE(nt) do {                                                  \
    float cc[4] = {0.f, 0.f, 0.f, 0.f};                                      \
    const float* kr = &Ks[((nt) * 8 + gid) * KSTRIDE];                       \
    _Pragma("unroll")                                                        \
    for (int ks = 0; ks < 8; ks++) {                                         \
        uint32_t b0 = __float_as_uint(kr[ks * 8 + tg]);                      \
        uint32_t b1 = __float_as_uint(kr[ks * 8 + tg + 4]);                  \
        mma16808t(cc, a[ks][0], a[ks][1], a[ks][2], a[ks][3], b0, b1);       \
    }                                                                        \
    s[(nt) * 4 + 0] = cc[0]; s[(nt) * 4 + 1] = cc[1];                        \
    s[(nt) * 4 + 2] = cc[2]; s[(nt) * 4 + 3] = cc[3];                        \
} while (0)

#define SCORE_MASK2(nt) do {                                                 \
    s[(nt) * 4 + 0] = -1e30f; s[(nt) * 4 + 1] = -1e30f;                      \
    s[(nt) * 4 + 2] = -1e30f; s[(nt) * 4 + 3] = -1e30f;                      \
    s[(nt) * 4 + 4] = -1e30f; s[(nt) * 4 + 5] = -1e30f;                      \
    s[(nt) * 4 + 6] = -1e30f; s[(nt) * 4 + 7] = -1e30f;                      \
} while (0)

// ---- one 8-key PV group (tf32): shuffle P into A-fragment layout, 8 MMAs --
#define PV_GROUP(g) do {                                                     \
    const int lb   = lane & ~3;                                              \
    const int srcA = lb | (tg >> 1);                                         \
    const int srcB = lb | 2 | (tg >> 1);                                     \
    float v00 = __shfl_sync(0xffffffffu, s[(g) * 4 + 0], srcA);              \
    float v01 = __shfl_sync(0xffffffffu, s[(g) * 4 + 1], srcA);              \
    float v10 = __shfl_sync(0xffffffffu, s[(g) * 4 + 2], srcA);              \
    float v11 = __shfl_sync(0xffffffffu, s[(g) * 4 + 3], srcA);              \
    float w00 = __shfl_sync(0xffffffffu, s[(g) * 4 + 0], srcB);              \
    float w01 = __shfl_sync(0xffffffffu, s[(g) * 4 + 1], srcB);              \
    float w10 = __shfl_sync(0xffffffffu, s[(g) * 4 + 2], srcB);              \
    float w11 = __shfl_sync(0xffffffffu, s[(g) * 4 + 3], srcB);              \
    const bool podd = (tg & 1);                                              \
    uint32_t pa0 = __float_as_uint(podd ? v01 : v00);                        \
    uint32_t pa1 = __float_as_uint(podd ? v11 : v10);                        \
    uint32_t pa2 = __float_as_uint(podd ? w01 : w00);                        \
    uint32_t pa3 = __float_as_uint(podd ? w11 : w10);                        \
    _Pragma("unroll")                                                        \
    for (int hn = 0; hn < 8; hn++) {                                         \
        const float* vr = &Vs[(hn * 8 + gid) * KSTRIDE + (g) * 8];           \
        uint32_t b0 = __float_as_uint(vr[tg]);                               \
        uint32_t b1 = __float_as_uint(vr[tg + 4]);                           \
        mma16808t(&O[hn * 4], pa0, pa1, pa2, pa3, b0, b1);                   \
    }                                                                        \
} while (0)

__global__ __launch_bounds__(256, 2)
void attn_mma(float* __restrict__ out)
{
    extern __shared__ char sm[];
    const uint32_t sb = smem_u32(sm);
    const int half = blockIdx.x;
    const int b    = blockIdx.y;
    const int tid  = threadIdx.x;
    const int lane = tid & 31;
    const int w    = tid >> 5;
    const int gid  = lane >> 2;
    const int tg   = lane & 3;
    const int qb   = half * 128 + w * 16;

    auto stage = [&](int c, int buf) {
        const int kn0 = c * 64;
        const uint32_t base = sb + buf * ABUF;
#pragma unroll
        for (int it = 0; it < 4; it++) {
            int i  = tid + 256 * it;
            int r  = i >> 4;
            int c4 = (i & 15) << 2;
            cp16(base + (uint32_t)(r * KSTRIDE + c4) * 4,
                 &KfG[((size_t)b * TT + kn0 + r) * HS + c4]);
        }
#pragma unroll
        for (int it = 0; it < 4; it++) {
            int i  = tid + 256 * it;
            int r  = i >> 4;
            int c4 = (i & 15) << 2;
            cp16(base + KBYTES + (uint32_t)(r * KSTRIDE + c4) * 4,
                 &VtfG[((size_t)b * HS + r) * TT + kn0 + c4]);
        }
        CP_COMMIT();
    };

    // Q A-fragments (tf32, pre-rounded+scaled fp32 from global).
    uint32_t a[8][4];
    {
        const float* q0 = &QfG[((size_t)b * TT + qb + gid) * HS];
        const float* q1 = q0 + 8 * HS;
#pragma unroll
        for (int ks = 0; ks < 8; ks++) {
            a[ks][0] = __float_as_uint(q0[ks * 8 + tg]);
            a[ks][1] = __float_as_uint(q1[ks * 8 + tg]);
            a[ks][2] = __float_as_uint(q0[ks * 8 + tg + 4]);
            a[ks][3] = __float_as_uint(q1[ks * 8 + tg + 4]);
        }
    }

    float O[32];
#pragma unroll
    for (int i = 0; i < 32; i++) O[i] = 0.f;
    float mr0 = -1e30f, mr1 = -1e30f, l0 = 0.f, l1 = 0.f;

    const int nch = (half + 1) * 2;
    stage(0, 0);
#pragma unroll 1
    for (int c = 0; c < nch; c++) {
        if (c < nch - 1) { stage(c + 1, (c + 1) & 1); CP_WAIT1(); } else { CP_WAIT0(); }
        __syncthreads();
        const int kn0 = c * 64;
        const int buf = c & 1;
        const float* Ks = reinterpret_cast<const float*>(sm + buf * ABUF);
        const float* Vs = reinterpret_cast<const float*>(sm + buf * ABUF + KBYTES);

        if (kn0 <= qb) {
            const bool diag = (kn0 + 63 > qb);
            const int ntmax = diag ? (((qb + 15 - kn0) >> 3) + 1) : 8;  // 2,4,6,8
            float s[32];

            // ---- scores ----
            if (!diag) {
                SCORE_TILE(0); SCORE_TILE(1); SCORE_TILE(2); SCORE_TILE(3);
                SCORE_TILE(4); SCORE_TILE(5); SCORE_TILE(6); SCORE_TILE(7);
            } else {
                SCORE_TILE(0); SCORE_TILE(1);
                if (ntmax > 2) { SCORE_TILE(2); SCORE_TILE(3); } else { SCORE_MASK2(2); }
                if (ntmax > 4) { SCORE_TILE(4); SCORE_TILE(5); } else { SCORE_MASK2(4); }
                if (ntmax > 6) { SCORE_TILE(6); SCORE_TILE(7); } else { SCORE_MASK2(6); }
                const int r0 = qb + gid, r1 = qb + 8 + gid;
#pragma unroll
                for (int nt = 0; nt < 8; nt++) {
                    const int col = kn0 + nt * 8 + 2 * tg;
                    if (col     > r0) s[nt * 4 + 0] = -1e30f;
                    if (col + 1 > r0) s[nt * 4 + 1] = -1e30f;
                    if (col     > r1) s[nt * 4 + 2] = -1e30f;
                    if (col + 1 > r1) s[nt * 4 + 3] = -1e30f;
                }
            }

            // ---- online softmax (base-2, MUFU ex2) ----
            float c0m = -1e30f, c1m = -1e30f;
#pragma unroll
            for (int nt = 0; nt < 8; nt++) {
                c0m = fmaxf(c0m, fmaxf(s[nt * 4 + 0], s[nt * 4 + 1]));
                c1m = fmaxf(c1m, fmaxf(s[nt * 4 + 2], s[nt * 4 + 3]));
            }
            c0m = fmaxf(c0m, __shfl_xor_sync(0xffffffffu, c0m, 1));
            c0m = fmaxf(c0m, __shfl_xor_sync(0xffffffffu, c0m, 2));
            c1m = fmaxf(c1m, __shfl_xor_sync(0xffffffffu, c1m, 1));
            c1m = fmaxf(c1m, __shfl_xor_sync(0xffffffffu, c1m, 2));
            const float mn0 = fmaxf(mr0, c0m), mn1 = fmaxf(mr1, c1m);
            const float corr0 = ex2f(mr0 - mn0), corr1 = ex2f(mr1 - mn1);
            mr0 = mn0; mr1 = mn1;

            float sum0 = 0.f, sum1 = 0.f;
#pragma unroll
            for (int nt = 0; nt < 8; nt++) {
                float p0 = ex2f(s[nt * 4 + 0] - mn0);
                float p1 = ex2f(s[nt * 4 + 1] - mn0);
                float p2 = ex2f(s[nt * 4 + 2] - mn1);
                float p3 = ex2f(s[nt * 4 + 3] - mn1);
                s[nt * 4 + 0] = p0; s[nt * 4 + 1] = p1;
                s[nt * 4 + 2] = p2; s[nt * 4 + 3] = p3;
                sum0 += p0 + p1; sum1 += p2 + p3;
            }
            sum0 += __shfl_xor_sync(0xffffffffu, sum0, 1);
            sum0 += __shfl_xor_sync(0xffffffffu, sum0, 2);
            sum1 += __shfl_xor_sync(0xffffffffu, sum1, 1);
            sum1 += __shfl_xor_sync(0xffffffffu, sum1, 2);
            l0 = l0 * corr0 + sum0;
            l1 = l1 * corr1 + sum1;
#pragma unroll
            for (int hn = 0; hn < 8; hn++) {
                O[hn * 4 + 0] *= corr0; O[hn * 4 + 1] *= corr0;
                O[hn * 4 + 2] *= corr1; O[hn * 4 + 3] *= corr1;
            }

            // ---- PV (tf32, P via quad-shuffle transpose) ----
            if (!diag) {
                PV_GROUP(0); PV_GROUP(1); PV_GROUP(2); PV_GROUP(3);
                PV_GROUP(4); PV_GROUP(5); PV_GROUP(6); PV_GROUP(7);
            } else {
                PV_GROUP(0); PV_GROUP(1);
                if (ntmax > 2) { PV_GROUP(2); PV_GROUP(3); }
                if (ntmax > 4) { PV_GROUP(4); PV_GROUP(5); }
                if (ntmax > 6) { PV_GROUP(6); PV_GROUP(7); }
            }
        }
        __syncthreads();
    }

    const float i0 = 1.f / l0, i1 = 1.f / l1;
    float* o0 = out + ((size_t)b * TT + qb + gid) * HS;
    float* o1 = o0 + 8 * HS;
#pragma unroll
    for (int hn = 0; hn < 8; hn++) {
        *reinterpret_cast<float2*>(&o0[hn * 8 + 2 * tg]) =
            make_float2(O[hn * 4 + 0] * i0, O[hn * 4 + 1] * i0);
        *reinterpret_cast<float2*>(&o1[hn * 8 + 2 * tg]) =
            make_float2(O[hn * 4 + 2] * i1, O[hn * 4 + 3] * i1);
    }
}

// ============================================================================
extern "C" void kernel_launch(void* const* d_in, const int* in_sizes, int n_in,
                              void* d_out, int out_size)
{
    const float* x  = (const float*)d_in[0];
    const float* Wq = (const float*)d_in[1];
    const float* Wk = (const float*)d_in[2];
    const float* Wv = (const float*)d_in[3];
    float* out = (float*)d_out;

    (void)in_sizes; (void)n_in; (void)out_size;

    prep_w<<<(384 * 192 + 255) / 256, 256>>>(Wq, Wk, Wv);

    cudaFuncSetAttribute(qkv_mma, cudaFuncAttributeMaxDynamicSharedMemorySize, QKV_SMEM);
    qkv_mma<<<2048, 256, QKV_SMEM>>>(x);

    cudaFuncSetAttribute(attn_mma, cudaFuncAttributeMaxDynamicSharedMemorySize, ATTN_SMEM);
    dim3 agrid(2, BB);
    attn_mma<<<agrid, 256, ATTN_SMEM>>>(out);
}

// round 13
// speedup vs baseline: 1.1787x; 1.0148x over previous
#include <cuda_runtime.h>
#include <cuda_bf16.h>
#include <cstdint>

#define BB   1024
#define TT   256
#define CC   384
#define HS   64

// Scratch (device globals: allocation-free).
// QfG: Q * SCALE2, tf32-RNA, row-major [b*T+t][hs]
// KfG: K, tf32-RNA, rows [b*T+t], hs PACKED within 8-groups: pos(h)=(h&~7)+(h&3)*2+((h>>2)&1)
// VtfG: V^T, tf32-RNA, [b][hs][t] with t PACKED within 8-groups (same pos())
// WpG: W concat tf32-RNA, pair-packed: ((k>>3)*4 + (k&3))*384 + n*2 + ((k>>2)&1)
__device__ __align__(16) float QfG[BB * TT * HS];
__device__ __align__(16) float KfG[BB * TT * HS];
__device__ __align__(16) float VtfG[BB * HS * TT];
__device__ __align__(16) float WpG[384 * 192];

// ---------------- helpers ----------------
__device__ __forceinline__ uint32_t smem_u32(const void* p) {
    uint32_t a;
    asm("{ .reg .u64 t; cvta.to.shared.u64 t, %1; cvt.u32.u64 %0, t; }" : "=r"(a) : "l"(p));
    return a;
}
__device__ __forceinline__ void cp16(uint32_t dst, const void* src) {
    asm volatile("cp.async.ca.shared.global [%0], [%1], 16;" :: "r"(dst), "l"(src) : "memory");
}
#define CP_COMMIT() asm volatile("cp.async.commit_group;" ::: "memory")
#define CP_WAIT1()  asm volatile("cp.async.wait_group 1;" ::: "memory")
#define CP_WAIT0()  asm volatile("cp.async.wait_group 0;" ::: "memory")

__device__ __forceinline__ uint32_t rna_tf32(uint32_t x) {
    uint32_t r;
    asm("cvt.rna.tf32.f32 %0, %1;" : "=r"(r) : "r"(x));
    return r;
}
__device__ __forceinline__ float rna_tf32_f(float x) {
    float r;
    asm("cvt.rna.tf32.f32 %0, %1;" : "=f"(r) : "f"(x));
    return r;
}

// MUFU exp2
__device__ __forceinline__ float ex2f(float x) {
    float r;
    asm("ex2.approx.f32 %0, %1;" : "=f"(r) : "f"(x));
    return r;
}
#define SCALE2 0.18033688f   // 0.125 * log2(e)

// within-8 pair-pack position
__device__ __forceinline__ int pk8(int h) {
    return (h & ~7) + (h & 3) * 2 + ((h >> 2) & 1);
}

// tf32 m16n8k8 MMA
__device__ __forceinline__ void mma16808t(float* c,
                                          uint32_t a0, uint32_t a1, uint32_t a2, uint32_t a3,
                                          uint32_t b0, uint32_t b1) {
    asm volatile(
        "mma.sync.aligned.m16n8k8.row.col.f32.tf32.tf32.f32 "
        "{%0,%1,%2,%3}, {%4,%5,%6,%7}, {%8,%9}, {%0,%1,%2,%3};"
        : "+f"(c[0]), "+f"(c[1]), "+f"(c[2]), "+f"(c[3])
        : "r"(a0), "r"(a1), "r"(a2), "r"(a3), "r"(b0), "r"(b1));
}

// ============================================================================
// Kernel 0: pack W pairs: element ((k>>3)*4+(k&3))*384 + n*2 + ((k>>2)&1).
// ============================================================================
__global__ void prep_w(const float* __restrict__ Wq,
                       const float* __restrict__ Wk,
                       const float* __restrict__ Wv)
{
    int idx = blockIdx.x * blockDim.x + threadIdx.x;
    if (idx >= 384 * 192) return;
    int k = idx / 192;
    int n = idx % 192;
    int m = n >> 6, hs = n & 63;
    const float* W = (m == 0) ? Wq : ((m == 1) ? Wk : Wv);
    float v = rna_tf32_f(W[k * HS + hs]);
    int g = k >> 3, q = k & 3, half = (k >> 2) & 1;
    WpG[((g * 4 + q) * 192 + n) * 2 + half] = v;
}

// ============================================================================
// Kernel 1: QKV projection, 1xTF32, cp.async double-buffered.
// B operands pair-packed: one LDS.64 per (b0,b1). Epilogue: Q row-major
// (pre-scaled), K hs-packed, V^T t-packed.
// ============================================================================
#define ASTRIDE 40
#define BP      392                 // packed-B row stride in floats (mod32==8 -> S=32)
#define AOFFB 0
#define BOFFB 20480
#define QBUF  46080                 // A 20480 + B 16*392*4=25088 -> 45568 (fits)
#define QKV_SMEM (2 * QBUF)         // 92160 B

__global__ __launch_bounds__(256, 2)
void qkv_mma(const float* __restrict__ X)
{
    extern __shared__ char sm[];
    const int tid  = threadIdx.x;
    const int lane = tid & 31;
    const int w    = tid >> 5;
    const int m0   = (w >> 1) * 32;
    const int n0   = (w & 1) * 96;
    const int gid  = lane >> 2;
    const int tg   = lane & 3;
    const size_t row0 = (size_t)blockIdx.x * 128;
    const uint32_t sb = smem_u32(sm);

    auto stage = [&](int c, int buf) {
        const int k0 = c * 32;
        const uint32_t base = sb + buf * QBUF;
#pragma unroll
        for (int it = 0; it < 4; it++) {
            int i  = tid + 256 * it;
            int r  = i >> 3;
            int c4 = (i & 7) << 2;
            cp16(base + AOFFB + (uint32_t)(r * ASTRIDE + c4) * 4,
                 &X[(row0 + r) * CC + k0 + c4]);
        }
        // packed B: 16 rows x 384 floats, row stride BP in smem
#pragma unroll
        for (int it = 0; it < 6; it++) {
            int i  = tid + 256 * it;           // 0..1535
            int r  = i / 96;                    // 0..15
            int cw = (i % 96) << 2;             // 0..380
            cp16(base + BOFFB + (uint32_t)(r * BP + cw) * 4,
                 &WpG[(size_t)(c * 16 + r) * 384 + cw]);
        }
        CP_COMMIT();
    };

    float acc[2][12][4] = {};

    stage(0, 0);
#pragma unroll 1
    for (int c = 0; c < 12; c++) {
        if (c < 11) { stage(c + 1, (c + 1) & 1); CP_WAIT1(); } else { CP_WAIT0(); }
        __syncthreads();
        const int buf = c & 1;
        const uint32_t* A  = reinterpret_cast<const uint32_t*>(sm + buf * QBUF + AOFFB);
        const float2*  Bp  = reinterpret_cast<const float2*>(sm + buf * QBUF + BOFFB);

#pragma unroll
        for (int ks = 0; ks < 4; ks++) {
            const int kc = ks * 8 + tg;
            uint32_t a[2][4];
#pragma unroll
            for (int mt = 0; mt < 2; mt++) {
                const int r = m0 + mt * 16 + gid;
                a[mt][0] = rna_tf32(A[r * ASTRIDE + kc]);
                a[mt][1] = rna_tf32(A[(r + 8) * ASTRIDE + kc]);
                a[mt][2] = rna_tf32(A[r * ASTRIDE + kc + 4]);
                a[mt][3] = rna_tf32(A[(r + 8) * ASTRIDE + kc + 4]);
            }
            const float2* brow = &Bp[(ks * 4 + tg) * (BP / 2)];
#pragma unroll
            for (int nt = 0; nt < 12; nt++) {
                const int col = n0 + nt * 8 + gid;
                float2 bb = brow[col];
                uint32_t b0 = __float_as_uint(bb.x);
                uint32_t b1 = __float_as_uint(bb.y);
                mma16808t(acc[0][nt], a[0][0], a[0][1], a[0][2], a[0][3], b0, b1);
                mma16808t(acc[1][nt], a[1][0], a[1][1], a[1][2], a[1][3], b0, b1);
            }
        }
        __syncthreads();
    }

    // --- epilogue ---
#pragma unroll
    for (int nt = 0; nt < 12; nt++) {
        const int colg = n0 + nt * 8 + 2 * tg;
        const int mat  = colg >> 6;
        const int hs0  = colg & 63;
#pragma unroll
        for (int mt = 0; mt < 2; mt++) {
            const size_t rowA = row0 + m0 + mt * 16 + gid;
            const size_t rowB = rowA + 8;
            const float* cc = acc[mt][nt];
            if (mat == 2) {
                // V^T with t packed within 8-groups
                const size_t baseA = (rowA >> 8) * (size_t)(HS * TT) + pk8((int)(rowA & 255));
                const size_t baseB = (rowB >> 8) * (size_t)(HS * TT) + pk8((int)(rowB & 255));
                VtfG[baseA + (size_t)hs0 * TT]       = rna_tf32_f(cc[0]);
                VtfG[baseA + (size_t)(hs0 + 1) * TT] = rna_tf32_f(cc[1]);
                VtfG[baseB + (size_t)hs0 * TT]       = rna_tf32_f(cc[2]);
                VtfG[baseB + (size_t)(hs0 + 1) * TT] = rna_tf32_f(cc[3]);
            } else if (mat == 0) {
                *reinterpret_cast<float2*>(&QfG[rowA * HS + hs0]) =
                    make_float2(rna_tf32_f(cc[0] * SCALE2), rna_tf32_f(cc[1] * SCALE2));
                *reinterpret_cast<float2*>(&QfG[rowB * HS + hs0]) =
                    make_float2(rna_tf32_f(cc[2] * SCALE2), rna_tf32_f(cc[3] * SCALE2));
            } else {
                // K with hs packed within 8-groups: pos(hs0+1) = pos(hs0)+2
                const int p = pk8(hs0);
                KfG[rowA * HS + p]     = rna_tf32_f(cc[0]);
                KfG[rowA * HS + p + 2] = rna_tf32_f(cc[1]);
                KfG[rowB * HS + p]     = rna_tf32_f(cc[2]);
                KfG[rowB * HS + p + 2] = rna_tf32_f(cc[3]);
            }
        }
    }
}

// ============================================================================
// Kernel 2: FA2 attention, all-tf32 MMAs, MUFU exp2, pair-packed K/V loads.
// Grid (2, 1024), 256 thr, 2 CTAs/SM, cp.async double-buffered 64-key chunks.
// ============================================================================
#define KSTRIDE 72                          // floats; 288B mod 128 = 32 (conflict-free)
#define KBYTES  (64 * KSTRIDE * 4)          // 18432
#define ABUF    (2 * KBYTES)                // K | Vt   -> 36864
#define ATTN_SMEM (2 * ABUF)                // 73728

// ---- one 8-key score n-tile (tf32); packed K -> LDS.64 pairs ----
#define SCORE_TILE(nt) do {                                                  \
    float cc[4] = {0.f, 0.f, 0.f, 0.f};                                      \
    const float2* kr = reinterpret_cast<const float2*>(                      \
        &Ks[((nt) * 8 + gid) * KSTRIDE]);                                    \
    _Pragma("unroll")                                                        \
    for (int ks = 0; ks < 8; ks++) {                                         \
        float2 bb = kr[ks * 4 + tg];                                         \
        mma16808t(cc, a[ks][0], a[ks][1], a[ks][2], a[ks][3],                \
                  __float_as_uint(bb.x), __float_as_uint(bb.y));             \
    }                                                                        \
    s[(nt) * 4 + 0] = cc[0]; s[(nt) * 4 + 1] = cc[1];                        \
    s[(nt) * 4 + 2] = cc[2]; s[(nt) * 4 + 3] = cc[3];                        \
} while (0)

#define SCORE_MASK2(nt) do {                                                 \
    s[(nt) * 4 + 0] = -1e30f; s[(nt) * 4 + 1] = -1e30f;                      \
    s[(nt) * 4 + 2] = -1e30f; s[(nt) * 4 + 3] = -1e30f;                      \
    s[(nt) * 4 + 4] = -1e30f; s[(nt) * 4 + 5] = -1e30f;                      \
    s[(nt) * 4 + 6] = -1e30f; s[(nt) * 4 + 7] = -1e30f;                      \
} while (0)

// ---- one 8-key PV group (tf32): shuffle P; packed V -> LDS.64 pairs ----
#define PV_GROUP(g) do {                                                     \
    const int lb   = lane & ~3;                                              \
    const int srcA = lb | (tg >> 1);                                         \
    const int srcB = lb | 2 | (tg >> 1);                                     \
    float v00 = __shfl_sync(0xffffffffu, s[(g) * 4 + 0], srcA);              \
    float v01 = __shfl_sync(0xffffffffu, s[(g) * 4 + 1], srcA);              \
    float v10 = __shfl_sync(0xffffffffu, s[(g) * 4 + 2], srcA);              \
    float v11 = __shfl_sync(0xffffffffu, s[(g) * 4 + 3], srcA);              \
    float w00 = __shfl_sync(0xffffffffu, s[(g) * 4 + 0], srcB);              \
    float w01 = __shfl_sync(0xffffffffu, s[(g) * 4 + 1], srcB);              \
    float w10 = __shfl_sync(0xffffffffu, s[(g) * 4 + 2], srcB);              \
    float w11 = __shfl_sync(0xffffffffu, s[(g) * 4 + 3], srcB);              \
    const bool podd = (tg & 1);                                              \
    uint32_t pa0 = __float_as_uint(podd ? v01 : v00);                        \
    uint32_t pa1 = __float_as_uint(podd ? v11 : v10);                        \
    uint32_t pa2 = __float_as_uint(podd ? w01 : w00);                        \
    uint32_t pa3 = __float_as_uint(podd ? w11 : w10);                        \
    _Pragma("unroll")                                                        \
    for (int hn = 0; hn < 8; hn++) {                                         \
        const float2* vr = reinterpret_cast<const float2*>(                  \
            &Vs[(hn * 8 + gid) * KSTRIDE]);                                  \
        float2 bb = vr[(g) * 4 + tg];                                        \
        mma16808t(&O[hn * 4], pa0, pa1, pa2, pa3,                            \
                  __float_as_uint(bb.x), __float_as_uint(bb.y));             \
    }                                                                        \
} while (0)

__global__ __launch_bounds__(256, 2)
void attn_mma(float* __restrict__ out)
{
    extern __shared__ char sm[];
    const uint32_t sb = smem_u32(sm);
    const int half = blockIdx.x;
    const int b    = blockIdx.y;
    const int tid  = threadIdx.x;
    const int lane = tid & 31;
    const int w    = tid >> 5;
    const int gid  = lane >> 2;
    const int tg   = lane & 3;
    const int qb   = half * 128 + w * 16;

    auto stage = [&](int c, int buf) {
        const int kn0 = c * 64;
        const uint32_t base = sb + buf * ABUF;
#pragma unroll
        for (int it = 0; it < 4; it++) {
            int i  = tid + 256 * it;
            int r  = i >> 4;
            int c4 = (i & 15) << 2;
            cp16(base + (uint32_t)(r * KSTRIDE + c4) * 4,
                 &KfG[((size_t)b * TT + kn0 + r) * HS + c4]);
        }
#pragma unroll
        for (int it = 0; it < 4; it++) {
            int i  = tid + 256 * it;
            int r  = i >> 4;
            int c4 = (i & 15) << 2;
            cp16(base + KBYTES + (uint32_t)(r * KSTRIDE + c4) * 4,
                 &VtfG[((size_t)b * HS + r) * TT + kn0 + c4]);
        }
        CP_COMMIT();
    };

    // Q A-fragments (tf32, pre-rounded+scaled fp32 from global; row-major).
    uint32_t a[8][4];
    {
        const float* q0 = &QfG[((size_t)b * TT + qb + gid) * HS];
        const float* q1 = q0 + 8 * HS;
#pragma unroll
        for (int ks = 0; ks < 8; ks++) {
            a[ks][0] = __float_as_uint(q0[ks * 8 + tg]);
            a[ks][1] = __float_as_uint(q1[ks * 8 + tg]);
            a[ks][2] = __float_as_uint(q0[ks * 8 + tg + 4]);
            a[ks][3] = __float_as_uint(q1[ks * 8 + tg + 4]);
        }
    }

    float O[32];
#pragma unroll
    for (int i = 0; i < 32; i++) O[i] = 0.f;
    float mr0 = -1e30f, mr1 = -1e30f, l0 = 0.f, l1 = 0.f;

    const int nch = (half + 1) * 2;
    stage(0, 0);
#pragma unroll 1
    for (int c = 0; c < nch; c++) {
        if (c < nch - 1) { stage(c + 1, (c + 1) & 1); CP_WAIT1(); } else { CP_WAIT0(); }
        __syncthreads();
        const int kn0 = c * 64;
        const int buf = c & 1;
        const float* Ks = reinterpret_cast<const float*>(sm + buf * ABUF);
        const float* Vs = reinterpret_cast<const float*>(sm + buf * ABUF + KBYTES);

        if (kn0 <= qb) {
            const bool diag = (kn0 + 63 > qb);
            const int ntmax = diag ? (((qb + 15 - kn0) >> 3) + 1) : 8;  // 2,4,6,8
            float s[32];

            // ---- scores ----
            if (!diag) {
                SCORE_TILE(0); SCORE_TILE(1); SCORE_TILE(2); SCORE_TILE(3);
                SCORE_TILE(4); SCORE_TILE(5); SCORE_TILE(6); SCORE_TILE(7);
            } else {
                SCORE_TILE(0); SCORE_TILE(1);
                if (ntmax > 2) { SCORE_TILE(2); SCORE_TILE(3); } else { SCORE_MASK2(2); }
                if (ntmax > 4) { SCORE_TILE(4); SCORE_TILE(5); } else { SCORE_MASK2(4); }
                if (ntmax > 6) { SCORE_TILE(6); SCORE_TILE(7); } else { SCORE_MASK2(6); }
                const int r0 = qb + gid, r1 = qb + 8 + gid;
#pragma unroll
                for (int nt = 0; nt < 8; nt++) {
                    const int col = kn0 + nt * 8 + 2 * tg;
                    if (col     > r0) s[nt * 4 + 0] = -1e30f;
                    if (col + 1 > r0) s[nt * 4 + 1] = -1e30f;
                    if (col     > r1) s[nt * 4 + 2] = -1e30f;
                    if (col + 1 > r1) s[nt * 4 + 3] = -1e30f;
                }
            }

            // ---- online softmax (base-2, MUFU ex2) ----
            float c0m = -1e30f, c1m = -1e30f;
#pragma unroll
            for (int nt = 0; nt < 8; nt++) {
                c0m = fmaxf(c0m, fmaxf(s[nt * 4 + 0], s[nt * 4 + 1]));
                c1m = fmaxf(c1m, fmaxf(s[nt * 4 + 2], s[nt * 4 + 3]));
            }
            c0m = fmaxf(c0m, __shfl_xor_sync(0xffffffffu, c0m, 1));
            c0m = fmaxf(c0m, __shfl_xor_sync(0xffffffffu, c0m, 2));
            c1m = fmaxf(c1m, __shfl_xor_sync(0xffffffffu, c1m, 1));
            c1m = fmaxf(c1m, __shfl_xor_sync(0xffffffffu, c1m, 2));
            const float mn0 = fmaxf(mr0, c0m), mn1 = fmaxf(mr1, c1m);
            const float corr0 = ex2f(mr0 - mn0), corr1 = ex2f(mr1 - mn1);
            mr0 = mn0; mr1 = mn1;

            float sum0 = 0.f, sum1 = 0.f;
#pragma unroll
            for (int nt = 0; nt < 8; nt++) {
                float p0 = ex2f(s[nt * 4 + 0] - mn0);
                float p1 = ex2f(s[nt * 4 + 1] - mn0);
                float p2 = ex2f(s[nt * 4 + 2] - mn1);
                float p3 = ex2f(s[nt * 4 + 3] - mn1);
                s[nt * 4 + 0] = p0; s[nt * 4 + 1] = p1;
                s[nt * 4 + 2] = p2; s[nt * 4 + 3] = p3;
                sum0 += p0 + p1; sum1 += p2 + p3;
            }
            sum0 += __shfl_xor_sync(0xffffffffu, sum0, 1);
            sum0 += __shfl_xor_sync(0xffffffffu, sum0, 2);
            sum1 += __shfl_xor_sync(0xffffffffu, sum1, 1);
            sum1 += __shfl_xor_sync(0xffffffffu, sum1, 2);
            l0 = l0 * corr0 + sum0;
            l1 = l1 * corr1 + sum1;
#pragma unroll
            for (int hn = 0; hn < 8; hn++) {
                O[hn * 4 + 0] *= corr0; O[hn * 4 + 1] *= corr0;
                O[hn * 4 + 2] *= corr1; O[hn * 4 + 3] *= corr1;
            }

            // ---- PV (tf32) ----
            if (!diag) {
                PV_GROUP(0); PV_GROUP(1); PV_GROUP(2); PV_GROUP(3);
                PV_GROUP(4); PV_GROUP(5); PV_GROUP(6); PV_GROUP(7);
            } else {
                PV_GROUP(0); PV_GROUP(1);
                if (ntmax > 2) { PV_GROUP(2); PV_GROUP(3); }
                if (ntmax > 4) { PV_GROUP(4); PV_GROUP(5); }
                if (ntmax > 6) { PV_GROUP(6); PV_GROUP(7); }
            }
        }
        __syncthreads();
    }

    const float i0 = 1.f / l0, i1 = 1.f / l1;
    float* o0 = out + ((size_t)b * TT + qb + gid) * HS;
    float* o1 = o0 + 8 * HS;
#pragma unroll
    for (int hn = 0; hn < 8; hn++) {
        *reinterpret_cast<float2*>(&o0[hn * 8 + 2 * tg]) =
            make_float2(O[hn * 4 + 0] * i0, O[hn * 4 + 1] * i0);
        *reinterpret_cast<float2*>(&o1[hn * 8 + 2 * tg]) =
            make_float2(O[hn * 4 + 2] * i1, O[hn * 4 + 3] * i1);
    }
}

// ============================================================================
extern "C" void kernel_launch(void* const* d_in, const int* in_sizes, int n_in,
                              void* d_out, int out_size)
{
    const float* x  = (const float*)d_in[0];
    const float* Wq = (const float*)d_in[1];
    const float* Wk = (const float*)d_in[2];
    const float* Wv = (const float*)d_in[3];
    float* out = (float*)d_out;

    (void)in_sizes; (void)n_in; (void)out_size;

    prep_w<<<(384 * 192 + 255) / 256, 256>>>(Wq, Wk, Wv);

    cudaFuncSetAttribute(qkv_mma, cudaFuncAttributeMaxDynamicSharedMemorySize, QKV_SMEM);
    qkv_mma<<<2048, 256, QKV_SMEM>>>(x);

    cudaFuncSetAttribute(attn_mma, cudaFuncAttributeMaxDynamicSharedMemorySize, ATTN_SMEM);
    dim3 agrid(2, BB);
    attn_mma<<<agrid, 256, ATTN_SMEM>>>(out);
}